// round 6
// baseline (speedup 1.0000x reference)
#include <cuda_runtime.h>
#include <math.h>
#include <stdint.h>

#define BB 8
#define NN 2048
#define HH 256
#define MM (BB*NN)
#define KNB 6
#define INFD 1e9f
typedef unsigned long long u64;

// ---------------- device scratch ----------------
__device__ float  g_h1[MM*HH];          // layer-1 output
__device__ float  g_norm[MM];
__device__ int    g_nbr[MM*KNB];
__device__ float  g_dist[MM*KNB];
__device__ float  g_w[MM*KNB];
__device__ float4 g_bf[2*16*4096];      // fragment-ready B: [L][chunk][4096 float4]

// ---------------- helpers ----------------
__device__ __forceinline__ uint32_t smem_u32(const void* p) {
    uint32_t a;
    asm("{ .reg .u64 t; cvta.to.shared.u64 t, %1; cvt.u32.u64 %0, t; }" : "=r"(a) : "l"(p));
    return a;
}
__device__ __forceinline__ uint32_t tf32r(float x) {
    uint32_t r; asm("cvt.rna.tf32.f32 %0, %1;" : "=r"(r) : "f"(x)); return r;
}
__device__ __forceinline__ float tf32f(float x) { return __uint_as_float(tf32r(x)); }

__device__ __forceinline__ void mma8(float* c, uint32_t a0, uint32_t a1,
                                     uint32_t a2, uint32_t a3,
                                     uint32_t b0, uint32_t b1) {
    asm volatile("mma.sync.aligned.m16n8k8.row.col.f32.tf32.tf32.f32 "
                 "{%0,%1,%2,%3}, {%4,%5,%6,%7}, {%8,%9}, {%0,%1,%2,%3};"
                 : "+f"(c[0]), "+f"(c[1]), "+f"(c[2]), "+f"(c[3])
                 : "r"(a0), "r"(a1), "r"(a2), "r"(a3), "r"(b0), "r"(b1));
}
__device__ __forceinline__ void cp16(uint32_t dst, const void* src) {
    asm volatile("cp.async.ca.shared.global [%0], [%1], 16;" :: "r"(dst), "l"(src) : "memory");
}

// ---------------- dynamic SMEM offsets for gemm (bytes) ----------------
#define BF0   0
#define BF1   65536
#define AF0   131072
#define AF1   163840
#define T_SI  196608
#define T_SW  199680
#define T_GAM 202752
#define T_BET 203776
#define T_R1  204800
#define T_R2  206848
#define SMEM_TOTAL 208896

// ---------------- row norms ----------------
__global__ void __launch_bounds__(256) norm_kernel(const float* __restrict__ h) {
    int warp = threadIdx.x >> 5, lane = threadIdx.x & 31;
    int row = blockIdx.x * 8 + warp;
    const float4* p = (const float4*)(h + (size_t)row * HH);
    float4 a = p[lane * 2], b = p[lane * 2 + 1];
    float s = a.x*a.x + a.y*a.y + a.z*a.z + a.w*a.w
            + b.x*b.x + b.y*b.y + b.z*b.z + b.w*b.w;
    #pragma unroll
    for (int o = 16; o; o >>= 1) s += __shfl_xor_sync(0xffffffffu, s, o);
    if (lane == 0) g_norm[row] = sqrtf(s);
}

// ---------------- brute-force kNN (top-6), u64 keys, 4 cands/iter ----------------
__global__ void __launch_bounds__(256) knn_kernel(const float* __restrict__ cent,
                                                  const unsigned char* __restrict__ pad) {
    __shared__ float2 tbl[NN];
    __shared__ u64    mk[32 * 64];

    int b = blockIdx.y;
    int tid = threadIdx.x;
    const float* cb = cent + (size_t)b * NN * 2;
    for (int j = tid; j < NN; j += 256) {
        float cx = cb[2 * j], cy = cb[2 * j + 1];
        if (pad[b * NN + j]) { cx = 1e30f; cy = 1e30f; }
        tbl[j] = make_float2(cx, cy);
    }
    __syncthreads();

    int g = tid >> 3, sub = tid & 7;
    int q = blockIdx.x * 32 + g;
    float2 qc = tbl[q];

    u64 bq[8];
    #pragma unroll
    for (int t = 0; t < 8; t++) bq[t] = 0xFFFFFFFFFFFFFFFFull;

    const float4* t4 = (const float4*)tbl;

    #pragma unroll 2
    for (int it = 0; it < 64; ++it) {
        float4 p0 = t4[it * 16 + sub * 2];
        float4 p1 = t4[it * 16 + sub * 2 + 1];
        int j0 = it * 32 + sub * 4;
        float dx0 = __fadd_rn(qc.x, -p0.x), dy0 = __fadd_rn(qc.y, -p0.y);
        float dx1 = __fadd_rn(qc.x, -p0.z), dy1 = __fadd_rn(qc.y, -p0.w);
        float dx2 = __fadd_rn(qc.x, -p1.x), dy2 = __fadd_rn(qc.y, -p1.y);
        float dx3 = __fadd_rn(qc.x, -p1.z), dy3 = __fadd_rn(qc.y, -p1.w);
        float d0 = __fadd_rn(__fmul_rn(dx0,dx0), __fmul_rn(dy0,dy0));
        float d1 = __fadd_rn(__fmul_rn(dx1,dx1), __fmul_rn(dy1,dy1));
        float d2 = __fadd_rn(__fmul_rn(dx2,dx2), __fmul_rn(dy2,dy2));
        float d3 = __fadd_rn(__fmul_rn(dx3,dx3), __fmul_rn(dy3,dy3));
        u64 k0 = ((u64)__float_as_uint(d0) << 32) | (uint32_t)(j0 + 0);
        u64 k1 = ((u64)__float_as_uint(d1) << 32) | (uint32_t)(j0 + 1);
        u64 k2 = ((u64)__float_as_uint(d2) << 32) | (uint32_t)(j0 + 2);
        u64 k3 = ((u64)__float_as_uint(d3) << 32) | (uint32_t)(j0 + 3);
        u64 kmin = min(min(k0, k1), min(k2, k3));
        if (kmin < bq[7]) {
            #define INS(kk) if ((kk) < bq[7]) {                                   \
                bq[7] = (kk);                                                     \
                _Pragma("unroll")                                                 \
                for (int t = 7; t > 0; --t) {                                     \
                    u64 lo_ = bq[t] < bq[t-1] ? bq[t] : bq[t-1];                  \
                    u64 hi_ = bq[t] < bq[t-1] ? bq[t-1] : bq[t];                  \
                    bq[t-1] = lo_; bq[t] = hi_;                                   \
                }                                                                 \
            }
            INS(k0); INS(k1); INS(k2); INS(k3);
            #undef INS
        }
    }

    #pragma unroll
    for (int t = 0; t < 8; t++) mk[g * 64 + sub * 8 + t] = bq[t];
    __syncwarp();

    if (sub == 0) {
        // merge 64 -> top-7 by (sqrt(d2)_bits, idx) lexicographic
        u64 st[7];
        #pragma unroll
        for (int t = 0; t < 7; t++) st[t] = 0xFFFFFFFFFFFFFFFFull;
        for (int e = 0; e < 64; ++e) {
            u64 v = mk[g * 64 + e];
            float d2v = __uint_as_float((uint32_t)(v >> 32));
            uint32_t idx = (uint32_t)v;
            float s = sqrtf(fmaxf(d2v, 0.f));
            u64 key = ((u64)__float_as_uint(s) << 32) | idx;
            if (key < st[6]) {
                st[6] = key;
                #pragma unroll
                for (int t = 6; t > 0; --t) {
                    u64 lo_ = st[t] < st[t-1] ? st[t] : st[t-1];
                    u64 hi_ = st[t] < st[t-1] ? st[t-1] : st[t];
                    st[t-1] = lo_; st[t] = hi_;
                }
            }
        }
        int row = b * NN + q;
        int outk = 0;
        bool skipped = false;
        for (int t = 0; t < 7 && outk < KNB; ++t) {
            uint32_t idx = (uint32_t)st[t];
            float dd = __uint_as_float((uint32_t)(st[t] >> 32));
            if (!skipped && (int)idx == q) { skipped = true; continue; }
            int oi = (int)idx;
            if (!(dd < 5e8f) || oi >= NN) { dd = INFD; oi = 0; }
            g_nbr[row * KNB + outk]  = oi;
            g_dist[row * KNB + outk] = dd;
            outk++;
        }
        for (; outk < KNB; ++outk) {
            g_nbr[row * KNB + outk] = 0;
            g_dist[row * KNB + outk] = INFD;
        }
    }
}

// ---------------- edge weights (parallel neighbor loads) ----------------
__global__ void __launch_bounds__(256) weight_kernel(const float* __restrict__ h,
                                                     const unsigned char* __restrict__ pad,
                                                     const int* __restrict__ tids) {
    int warp = threadIdx.x >> 5, lane = threadIdx.x & 31;
    int row = blockIdx.x * 8 + warp;
    int b = row / NN;

    const float4* hp = (const float4*)(h + (size_t)row * HH);
    float4 qa = hp[lane * 2], qb = hp[lane * 2 + 1];
    float nq = fmaxf(g_norm[row], 1e-12f);

    int   nb[6]; float dk[6];
    #pragma unroll
    for (int k = 0; k < KNB; k++) {
        nb[k] = g_nbr[row * KNB + k];
        dk[k] = g_dist[row * KNB + k];
    }
    // all 12 neighbor vector loads issued before any math
    float4 na[6], nbv[6];
    #pragma unroll
    for (int k = 0; k < KNB; k++) {
        const float4* np = (const float4*)(h + (size_t)(b * NN + nb[k]) * HH);
        na[k]  = np[lane * 2];
        nbv[k] = np[lane * 2 + 1];
    }
    float dot[6];
    #pragma unroll
    for (int k = 0; k < KNB; k++) {
        dot[k] = qa.x*na[k].x + qa.y*na[k].y + qa.z*na[k].z + qa.w*na[k].w
               + qb.x*nbv[k].x + qb.y*nbv[k].y + qb.z*nbv[k].z + qb.w*nbv[k].w;
    }
    #pragma unroll
    for (int o = 16; o; o >>= 1) {
        #pragma unroll
        for (int k = 0; k < KNB; k++)
            dot[k] += __shfl_xor_sync(0xffffffffu, dot[k], o);
    }

    if (lane == 0) {
        float invd[6], sim[6]; bool val[6];
        float sum_inv = 0.f, sum_sim = 0.f;
        #pragma unroll
        for (int k = 0; k < KNB; k++) {
            float nn = fmaxf(g_norm[b * NN + nb[k]], 1e-12f);
            bool v = dk[k] < 5e8f;
            float s  = v ? fmaxf(dot[k] / (nq * nn), 0.f) : 0.f;
            float id = v ? (1.f / fmaxf(dk[k], 1e-4f)) : 0.f;
            invd[k] = id; sim[k] = s; val[k] = v;
            sum_inv += id; sum_sim += s;
        }
        bool pq = pad[row] != 0;
        int tq = tids[row];
        float rs = 1.f / fmaxf(sum_inv, 1e-8f);
        float rm = 1.f / fmaxf(sum_sim, 1e-8f);
        float w[6]; float tot = 0.f;
        #pragma unroll
        for (int k = 0; k < KNB; k++) {
            float wk = 0.6f * invd[k] * rs + 0.4f * sim[k] * rm;
            int tnb = tids[b * NN + nb[k]];
            if (val[k] && (tq != tnb)) wk *= 1.2f;
            w[k] = wk; tot += wk;
        }
        float rt = 1.f / fmaxf(tot, 1e-8f);
        #pragma unroll
        for (int k = 0; k < KNB; k++)
            g_w[row * KNB + k] = pq ? 0.f : w[k] * rt;
    }
}

// ---------------- weight pre-split into fragment-ready layout ----------------
// g_bf[(L*16+c)*4096 + f], f = ((nf*4+k8)*32 + lane):
//   n = (nf>>3)*64 + (nf&7)*8 + (lane>>2), i = lane&3, kc = k8*8 + i
//   ksrc = (c&7)*32 + kc, W = (c<8 ? Ws : Wn)[L]
//   float4 = (hi(W[n][ksrc]), hi(W[n][ksrc+4]), lo(W[n][ksrc]), lo(W[n][ksrc+4]))
__global__ void __launch_bounds__(256) wsplit_kernel(const float* __restrict__ Ws1,
                                                     const float* __restrict__ Wn1,
                                                     const float* __restrict__ Ws2,
                                                     const float* __restrict__ Wn2) {
    int idx = blockIdx.x * 256 + threadIdx.x;   // 0..131071
    int L   = idx >> 16;
    int rem = idx & 65535;
    int c   = rem >> 12;
    int f   = rem & 4095;
    int lane = f & 31;
    int k8   = (f >> 5) & 3;
    int nf   = f >> 7;
    int n  = (nf >> 3) * 64 + (nf & 7) * 8 + (lane >> 2);
    int i  = lane & 3;
    int ks = (c & 7) * 32 + k8 * 8 + i;
    const float* W = (L == 0) ? (c < 8 ? Ws1 : Wn1) : (c < 8 ? Ws2 : Wn2);
    float w0 = W[n * 256 + ks];
    float w1 = W[n * 256 + ks + 4];
    float h0 = tf32f(w0), h1 = tf32f(w1);
    float l0 = tf32f(w0 - h0), l1 = tf32f(w1 - h1);
    g_bf[idx] = make_float4(h0, h1, l0, l1);
}

// ---------------- fused tf32x3 GEMM (M=128,N=256,K=512) + agg + GELU + LN + residual ----------------
__global__ void __launch_bounds__(256, 1) gemm_ln_mma(
    const float* __restrict__ hin, int L,
    const float* __restrict__ gv, const float* __restrict__ bv,
    const unsigned char* __restrict__ pad,
    float* __restrict__ hout, int zero_pad)
{
    extern __shared__ char sm[];
    uint32_t sb = smem_u32(sm);
    int tid = threadIdx.x;
    int m0 = blockIdx.x * 128;
    int bbase = (m0 >> 11) * NN;
    int wid = tid >> 5, lane = tid & 31;
    int mw = wid >> 2, nw = wid & 3;        // warp grid 2(M) x 4(N)
    int g = lane >> 2, i = lane & 3;

    int*   si   = (int*)(sm + T_SI);
    float* sw   = (float*)(sm + T_SW);
    float* sgam = (float*)(sm + T_GAM);
    float* sbet = (float*)(sm + T_BET);
    float* red1 = (float*)(sm + T_R1);
    float* red2 = (float*)(sm + T_R2);

    for (int e = tid; e < 128 * KNB; e += 256) {
        int r = e / KNB, k = e % KNB;
        si[e] = g_nbr[(size_t)(m0 + r) * KNB + k];
        sw[e] = g_w[(size_t)(m0 + r) * KNB + k];
    }
    sgam[tid] = gv[tid];
    sbet[tid] = bv[tid];
    __syncthreads();

    float acc[4][8][4];
    #pragma unroll
    for (int a = 0; a < 4; a++)
        #pragma unroll
        for (int b2 = 0; b2 < 8; b2++)
            #pragma unroll
            for (int c2 = 0; c2 < 4; c2++) acc[a][b2][c2] = 0.f;

    // ---- staging helpers ----
    auto stage_A = [&](int c, int afoff) {
        int k0 = (c & 7) * 32;
        float* af = (float*)(sm + afoff);
        #pragma unroll
        for (int t = 0; t < 4; ++t) {
            int fidx = t * 256 + tid;
            int r = fidx >> 3, q4 = fidx & 7;
            float4 v;
            if (c < 8) {
                v = *(const float4*)(hin + (size_t)(m0 + r) * HH + k0 + q4 * 4);
            } else {
                v = make_float4(0.f, 0.f, 0.f, 0.f);
                #pragma unroll
                for (int j = 0; j < KNB; ++j) {
                    float wj = sw[r * KNB + j];
                    const float4 nv = *(const float4*)(hin +
                        (size_t)(bbase + si[r * KNB + j]) * HH + k0 + q4 * 4);
                    v.x = fmaf(wj, nv.x, v.x);
                    v.y = fmaf(wj, nv.y, v.y);
                    v.z = fmaf(wj, nv.z, v.z);
                    v.w = fmaf(wj, nv.w, v.w);
                }
            }
            float hx = tf32f(v.x), hy = tf32f(v.y), hz = tf32f(v.z), hw = tf32f(v.w);
            float lx = tf32f(v.x - hx), ly = tf32f(v.y - hy);
            float lz = tf32f(v.z - hz), lw = tf32f(v.w - hw);
            int mf = ((r >> 6) << 2) | ((r >> 4) & 3);
            int gg = r & 7, rowsel = (r >> 3) & 1;
            int k8 = q4 >> 1, p = q4 & 1;
            int comp = rowsel + 2 * p;
            int base = ((mf * 4 + k8) * 32 + gg * 4) * 4 + comp;
            af[base + 0]  = hx; af[base + 4]  = hy;
            af[base + 8]  = hz; af[base + 12] = hw;
            af[4096 + base + 0]  = lx; af[4096 + base + 4]  = ly;
            af[4096 + base + 8]  = lz; af[4096 + base + 12] = lw;
        }
    };
    auto issue_B = [&](int c, int bfoff) {
        const float4* src = g_bf + ((size_t)(L * 16 + c) << 12);
        #pragma unroll
        for (int j = 0; j < 16; ++j) {
            int f = j * 256 + tid;
            cp16(sb + bfoff + f * 16, src + f);
        }
        asm volatile("cp.async.commit_group;" ::: "memory");
    };

    // prologue
    issue_B(0, BF0);
    stage_A(0, AF0);

    #pragma unroll 1
    for (int c = 0; c < 16; ++c) {
        int cur = c & 1;
        if (c < 15) {
            issue_B(c + 1, cur ? BF0 : BF1);
            stage_A(c + 1, cur ? AF0 : AF1);
            asm volatile("cp.async.wait_group 1;" ::: "memory");
        } else {
            asm volatile("cp.async.wait_group 0;" ::: "memory");
        }
        __syncthreads();

        const float4* afh = (const float4*)(sm + (cur ? AF1 : AF0));
        const float4* afl = (const float4*)(sm + (cur ? AF1 : AF0) + 16384);
        const float4* bf  = (const float4*)(sm + (cur ? BF1 : BF0));

        #pragma unroll
        for (int k8 = 0; k8 < 4; ++k8) {
            float4 fah[4], fal[4];
            #pragma unroll
            for (int mf = 0; mf < 4; ++mf) {
                fah[mf] = afh[((mw * 4 + mf) * 4 + k8) * 32 + lane];
                fal[mf] = afl[((mw * 4 + mf) * 4 + k8) * 32 + lane];
            }
            #pragma unroll
            for (int fnp = 0; fnp < 4; ++fnp) {
                float4 B0 = bf[((nw * 8 + fnp * 2 + 0) * 4 + k8) * 32 + lane];
                float4 B1 = bf[((nw * 8 + fnp * 2 + 1) * 4 + k8) * 32 + lane];
                uint32_t bh[2][2] = {{__float_as_uint(B0.x), __float_as_uint(B0.y)},
                                     {__float_as_uint(B1.x), __float_as_uint(B1.y)}};
                uint32_t bl[2][2] = {{__float_as_uint(B0.z), __float_as_uint(B0.w)},
                                     {__float_as_uint(B1.z), __float_as_uint(B1.w)}};
                // pass 1: hi*hi
                #pragma unroll
                for (int f2 = 0; f2 < 2; ++f2)
                    #pragma unroll
                    for (int mf = 0; mf < 4; ++mf)
                        mma8(acc[mf][fnp * 2 + f2],
                             __float_as_uint(fah[mf].x), __float_as_uint(fah[mf].y),
                             __float_as_uint(fah[mf].z), __float_as_uint(fah[mf].w),
                             bh[f2][0], bh[f2][1]);
                // pass 2: hi*lo
                #pragma unroll
                for (int f2 = 0; f2 < 2; ++f2)
                    #pragma unroll
                    for (int mf = 0; mf < 4; ++mf)
                        mma8(acc[mf][fnp * 2 + f2],
                             __float_as_uint(fah[mf].x), __float_as_uint(fah[mf].y),
                             __float_as_uint(fah[mf].z), __float_as_uint(fah[mf].w),
                             bl[f2][0], bl[f2][1]);
                // pass 3: lo*hi
                #pragma unroll
                for (int f2 = 0; f2 < 2; ++f2)
                    #pragma unroll
                    for (int mf = 0; mf < 4; ++mf)
                        mma8(acc[mf][fnp * 2 + f2],
                             __float_as_uint(fal[mf].x), __float_as_uint(fal[mf].y),
                             __float_as_uint(fal[mf].z), __float_as_uint(fal[mf].w),
                             bh[f2][0], bh[f2][1]);
            }
        }
        __syncthreads();
    }

    // ---- epilogue: GELU -> LN -> residual -> store ----
    float s1[8], s2[8];
    #pragma unroll
    for (int rs = 0; rs < 8; ++rs) { s1[rs] = 0.f; s2[rs] = 0.f; }
    #pragma unroll
    for (int fm = 0; fm < 4; ++fm)
        #pragma unroll
        for (int fn = 0; fn < 8; ++fn)
            #pragma unroll
            for (int cc = 0; cc < 4; ++cc) {
                float x = acc[fm][fn][cc];
                float gl = 0.5f * x * (1.0f + erff(x * 0.70710678118654752f));
                acc[fm][fn][cc] = gl;
                int rs = fm * 2 + (cc >> 1);
                s1[rs] += gl;
                s2[rs] = fmaf(gl, gl, s2[rs]);
            }
    #pragma unroll
    for (int rs = 0; rs < 8; ++rs) {
        #pragma unroll
        for (int o = 1; o <= 2; o <<= 1) {
            s1[rs] += __shfl_xor_sync(0xffffffffu, s1[rs], o);
            s2[rs] += __shfl_xor_sync(0xffffffffu, s2[rs], o);
        }
    }
    if (i == 0) {
        #pragma unroll
        for (int rs = 0; rs < 8; ++rs) {
            int fm = rs >> 1, rowsel = rs & 1;
            int row_l = mw * 64 + fm * 16 + rowsel * 8 + g;
            red1[row_l * 4 + nw] = s1[rs];
            red2[row_l * 4 + nw] = s2[rs];
        }
    }
    __syncthreads();

    #pragma unroll
    for (int fm = 0; fm < 4; ++fm) {
        #pragma unroll
        for (int rowsel = 0; rowsel < 2; ++rowsel) {
            int row_l = mw * 64 + fm * 16 + rowsel * 8 + g;
            int row_g = m0 + row_l;
            float st  = red1[row_l * 4 + 0] + red1[row_l * 4 + 1]
                      + red1[row_l * 4 + 2] + red1[row_l * 4 + 3];
            float st2 = red2[row_l * 4 + 0] + red2[row_l * 4 + 1]
                      + red2[row_l * 4 + 2] + red2[row_l * 4 + 3];
            float mu   = st * (1.f / HH);
            float var  = fmaf(-mu, mu, st2 * (1.f / HH));
            float rstd = rsqrtf(var + 1e-5f);
            bool pz = (zero_pad != 0) && (pad[row_g] != 0);
            #pragma unroll
            for (int fn = 0; fn < 8; ++fn) {
                int col = nw * 64 + fn * 8 + 2 * i;
                float v0 = acc[fm][fn][rowsel * 2 + 0];
                float v1 = acc[fm][fn][rowsel * 2 + 1];
                float2 res = *(const float2*)(hin + (size_t)row_g * HH + col);
                float2 o;
                o.x = pz ? 0.f : res.x + (v0 - mu) * rstd * sgam[col]     + sbet[col];
                o.y = pz ? 0.f : res.y + (v1 - mu) * rstd * sgam[col + 1] + sbet[col + 1];
                *(float2*)(hout + (size_t)row_g * HH + col) = o;
            }
        }
    }
}

// ---------------- launcher ----------------
extern "C" void kernel_launch(void* const* d_in, const int* in_sizes, int n_in,
                              void* d_out, int out_size) {
    const float*         h0   = (const float*)d_in[0];
    const unsigned char* pad  = (const unsigned char*)d_in[1];
    const float*         cent = (const float*)d_in[2];
    const int*           tids = (const int*)d_in[3];
    const float* Ws1 = (const float*)d_in[4];
    const float* Wn1 = (const float*)d_in[5];
    const float* g1  = (const float*)d_in[6];
    const float* b1  = (const float*)d_in[7];
    const float* Ws2 = (const float*)d_in[8];
    const float* Wn2 = (const float*)d_in[9];
    const float* g2  = (const float*)d_in[10];
    const float* b2  = (const float*)d_in[11];
    float* out = (float*)d_out;

    float* h1;
    cudaGetSymbolAddress((void**)&h1, g_h1);

    cudaFuncSetAttribute(gemm_ln_mma, cudaFuncAttributeMaxDynamicSharedMemorySize, SMEM_TOTAL);

    norm_kernel  <<<MM / 8, 256>>>(h0);                       // 0
    knn_kernel   <<<dim3(NN / 32, BB), 256>>>(cent, pad);     // 1
    weight_kernel<<<MM / 8, 256>>>(h0, pad, tids);            // 2
    wsplit_kernel<<<512, 256>>>(Ws1, Wn1, Ws2, Wn2);          // 3
    gemm_ln_mma<<<MM / 128, 256, SMEM_TOTAL>>>(h0, 0, g1, b1, pad, h1, 0);   // 4
    gemm_ln_mma<<<MM / 128, 256, SMEM_TOTAL>>>(h1, 1, g2, b2, pad, out, 1);  // 5 (profiled)
}

// round 7
// speedup vs baseline: 1.0073x; 1.0073x over previous
#include <cuda_runtime.h>
#include <math.h>
#include <stdint.h>

#define BB 8
#define NN 2048
#define HH 256
#define MM (BB*NN)
#define KNB 6
#define INFD 1e9f
typedef unsigned long long u64;

// ---------------- device scratch ----------------
__device__ float g_h1[MM*HH];          // layer-1 output
__device__ float g_norm[MM];
__device__ int   g_nbr[MM*KNB];
__device__ float g_dist[MM*KNB];
__device__ float g_w[MM*KNB];
__device__ float g_whi[2*256*512];     // tf32-hi of [Ws;Wn] per layer, [n][kk]
__device__ float g_wlo[2*256*512];     // tf32-lo

// ---------------- helpers ----------------
__device__ __forceinline__ uint32_t smem_u32(const void* p) {
    uint32_t a;
    asm("{ .reg .u64 t; cvta.to.shared.u64 t, %1; cvt.u32.u64 %0, t; }" : "=r"(a) : "l"(p));
    return a;
}
__device__ __forceinline__ uint32_t tf32r(float x) {
    uint32_t r; asm("cvt.rna.tf32.f32 %0, %1;" : "=r"(r) : "f"(x)); return r;
}
__device__ __forceinline__ float tf32f(float x) { return __uint_as_float(tf32r(x)); }

__device__ __forceinline__ void mma8(float* c, uint32_t a0, uint32_t a1,
                                     uint32_t a2, uint32_t a3,
                                     uint32_t b0, uint32_t b1) {
    asm volatile("mma.sync.aligned.m16n8k8.row.col.f32.tf32.tf32.f32 "
                 "{%0,%1,%2,%3}, {%4,%5,%6,%7}, {%8,%9}, {%0,%1,%2,%3};"
                 : "+f"(c[0]), "+f"(c[1]), "+f"(c[2]), "+f"(c[3])
                 : "r"(a0), "r"(a1), "r"(a2), "r"(a3), "r"(b0), "r"(b1));
}
__device__ __forceinline__ void cp16(uint32_t dst, const void* src) {
    asm volatile("cp.async.ca.shared.global [%0], [%1], 16;" :: "r"(dst), "l"(src) : "memory");
}

// ---------------- SMEM layout for gemm (bytes) ----------------
#define PADK 36
#define OFF_AHI  0
#define OFF_ALO  9216
#define OFF_BHI  18432
#define OFF_BLO  55296
#define OFF_SI   92160
#define OFF_SW   93696
#define OFF_R1   95232
#define OFF_R2   96256
#define OFF_GAM  97280
#define OFF_BET  98304
#define SMEM_TOTAL 99328

// ---------------- row norms ----------------
__global__ void __launch_bounds__(256) norm_kernel(const float* __restrict__ h) {
    int warp = threadIdx.x >> 5, lane = threadIdx.x & 31;
    int row = blockIdx.x * 8 + warp;
    const float4* p = (const float4*)(h + (size_t)row * HH);
    float4 a = p[lane * 2], b = p[lane * 2 + 1];
    float s = a.x*a.x + a.y*a.y + a.z*a.z + a.w*a.w
            + b.x*b.x + b.y*b.y + b.z*b.z + b.w*b.w;
    #pragma unroll
    for (int o = 16; o; o >>= 1) s += __shfl_xor_sync(0xffffffffu, s, o);
    if (lane == 0) g_norm[row] = sqrtf(s);
}

// ---------------- brute-force kNN (top-6), u64 keys, 4 cands/iter ----------------
__global__ void __launch_bounds__(256) knn_kernel(const float* __restrict__ cent,
                                                  const unsigned char* __restrict__ pad) {
    __shared__ float2 tbl[NN];
    __shared__ u64    mk[32 * 64];

    int b = blockIdx.y;
    int tid = threadIdx.x;
    const float* cb = cent + (size_t)b * NN * 2;
    for (int j = tid; j < NN; j += 256) {
        float cx = cb[2 * j], cy = cb[2 * j + 1];
        if (pad[b * NN + j]) { cx = 1e30f; cy = 1e30f; }
        tbl[j] = make_float2(cx, cy);
    }
    __syncthreads();

    int g = tid >> 3, sub = tid & 7;
    int q = blockIdx.x * 32 + g;
    float2 qc = tbl[q];

    u64 bq[8];
    #pragma unroll
    for (int t = 0; t < 8; t++) bq[t] = 0xFFFFFFFFFFFFFFFFull;

    const float4* t4 = (const float4*)tbl;

    #pragma unroll 2
    for (int it = 0; it < 64; ++it) {
        float4 p0 = t4[it * 16 + sub * 2];
        float4 p1 = t4[it * 16 + sub * 2 + 1];
        int j0 = it * 32 + sub * 4;
        float dx0 = __fadd_rn(qc.x, -p0.x), dy0 = __fadd_rn(qc.y, -p0.y);
        float dx1 = __fadd_rn(qc.x, -p0.z), dy1 = __fadd_rn(qc.y, -p0.w);
        float dx2 = __fadd_rn(qc.x, -p1.x), dy2 = __fadd_rn(qc.y, -p1.y);
        float dx3 = __fadd_rn(qc.x, -p1.z), dy3 = __fadd_rn(qc.y, -p1.w);
        float d0 = __fadd_rn(__fmul_rn(dx0,dx0), __fmul_rn(dy0,dy0));
        float d1 = __fadd_rn(__fmul_rn(dx1,dx1), __fmul_rn(dy1,dy1));
        float d2 = __fadd_rn(__fmul_rn(dx2,dx2), __fmul_rn(dy2,dy2));
        float d3 = __fadd_rn(__fmul_rn(dx3,dx3), __fmul_rn(dy3,dy3));
        u64 k0 = ((u64)__float_as_uint(d0) << 32) | (uint32_t)(j0 + 0);
        u64 k1 = ((u64)__float_as_uint(d1) << 32) | (uint32_t)(j0 + 1);
        u64 k2 = ((u64)__float_as_uint(d2) << 32) | (uint32_t)(j0 + 2);
        u64 k3 = ((u64)__float_as_uint(d3) << 32) | (uint32_t)(j0 + 3);
        u64 kmin = min(min(k0, k1), min(k2, k3));
        if (kmin < bq[7]) {
            #define INS(kk) if ((kk) < bq[7]) {                                   \
                bq[7] = (kk);                                                     \
                _Pragma("unroll")                                                 \
                for (int t = 7; t > 0; --t) {                                     \
                    u64 lo_ = bq[t] < bq[t-1] ? bq[t] : bq[t-1];                  \
                    u64 hi_ = bq[t] < bq[t-1] ? bq[t-1] : bq[t];                  \
                    bq[t-1] = lo_; bq[t] = hi_;                                   \
                }                                                                 \
            }
            INS(k0); INS(k1); INS(k2); INS(k3);
            #undef INS
        }
    }

    #pragma unroll
    for (int t = 0; t < 8; t++) mk[g * 64 + sub * 8 + t] = bq[t];
    __syncwarp();

    if (sub == 0) {
        // merge 64 -> top-7 by (sqrt(d2)_bits, idx) lexicographic
        u64 st[7];
        #pragma unroll
        for (int t = 0; t < 7; t++) st[t] = 0xFFFFFFFFFFFFFFFFull;
        for (int e = 0; e < 64; ++e) {
            u64 v = mk[g * 64 + e];
            float d2v = __uint_as_float((uint32_t)(v >> 32));
            uint32_t idx = (uint32_t)v;
            float s = sqrtf(fmaxf(d2v, 0.f));
            u64 key = ((u64)__float_as_uint(s) << 32) | idx;
            if (key < st[6]) {
                st[6] = key;
                #pragma unroll
                for (int t = 6; t > 0; --t) {
                    u64 lo_ = st[t] < st[t-1] ? st[t] : st[t-1];
                    u64 hi_ = st[t] < st[t-1] ? st[t-1] : st[t];
                    st[t-1] = lo_; st[t] = hi_;
                }
            }
        }
        int row = b * NN + q;
        int outk = 0;
        bool skipped = false;
        for (int t = 0; t < 7 && outk < KNB; ++t) {
            uint32_t idx = (uint32_t)st[t];
            float dd = __uint_as_float((uint32_t)(st[t] >> 32));
            if (!skipped && (int)idx == q) { skipped = true; continue; }
            int oi = (int)idx;
            if (!(dd < 5e8f) || oi >= NN) { dd = INFD; oi = 0; }
            g_nbr[row * KNB + outk]  = oi;
            g_dist[row * KNB + outk] = dd;
            outk++;
        }
        for (; outk < KNB; ++outk) {
            g_nbr[row * KNB + outk] = 0;
            g_dist[row * KNB + outk] = INFD;
        }
    }
}

// ---------------- edge weights (parallel neighbor loads) ----------------
__global__ void __launch_bounds__(256) weight_kernel(const float* __restrict__ h,
                                                     const unsigned char* __restrict__ pad,
                                                     const int* __restrict__ tids) {
    int warp = threadIdx.x >> 5, lane = threadIdx.x & 31;
    int row = blockIdx.x * 8 + warp;
    int b = row / NN;

    const float4* hp = (const float4*)(h + (size_t)row * HH);
    float4 qa = hp[lane * 2], qb = hp[lane * 2 + 1];
    float nq = fmaxf(g_norm[row], 1e-12f);

    int   nb[6]; float dk[6];
    #pragma unroll
    for (int k = 0; k < KNB; k++) {
        nb[k] = g_nbr[row * KNB + k];
        dk[k] = g_dist[row * KNB + k];
    }
    float4 na[6], nbv[6];
    #pragma unroll
    for (int k = 0; k < KNB; k++) {
        const float4* np = (const float4*)(h + (size_t)(b * NN + nb[k]) * HH);
        na[k]  = np[lane * 2];
        nbv[k] = np[lane * 2 + 1];
    }
    float dot[6];
    #pragma unroll
    for (int k = 0; k < KNB; k++) {
        dot[k] = qa.x*na[k].x + qa.y*na[k].y + qa.z*na[k].z + qa.w*na[k].w
               + qb.x*nbv[k].x + qb.y*nbv[k].y + qb.z*nbv[k].z + qb.w*nbv[k].w;
    }
    #pragma unroll
    for (int o = 16; o; o >>= 1) {
        #pragma unroll
        for (int k = 0; k < KNB; k++)
            dot[k] += __shfl_xor_sync(0xffffffffu, dot[k], o);
    }

    if (lane == 0) {
        float invd[6], sim[6]; bool val[6];
        float sum_inv = 0.f, sum_sim = 0.f;
        #pragma unroll
        for (int k = 0; k < KNB; k++) {
            float nn = fmaxf(g_norm[b * NN + nb[k]], 1e-12f);
            bool v = dk[k] < 5e8f;
            float s  = v ? fmaxf(dot[k] / (nq * nn), 0.f) : 0.f;
            float id = v ? (1.f / fmaxf(dk[k], 1e-4f)) : 0.f;
            invd[k] = id; sim[k] = s; val[k] = v;
            sum_inv += id; sum_sim += s;
        }
        bool pq = pad[row] != 0;
        int tq = tids[row];
        float rs = 1.f / fmaxf(sum_inv, 1e-8f);
        float rm = 1.f / fmaxf(sum_sim, 1e-8f);
        float w[6]; float tot = 0.f;
        #pragma unroll
        for (int k = 0; k < KNB; k++) {
            float wk = 0.6f * invd[k] * rs + 0.4f * sim[k] * rm;
            int tnb = tids[b * NN + nb[k]];
            if (val[k] && (tq != tnb)) wk *= 1.2f;
            w[k] = wk; tot += wk;
        }
        float rt = 1.f / fmaxf(tot, 1e-8f);
        #pragma unroll
        for (int k = 0; k < KNB; k++)
            g_w[row * KNB + k] = pq ? 0.f : w[k] * rt;
    }
}

// ---------------- weight tf32 hi/lo pre-split: g_whi/g_wlo[L][n][kk] ----------------
__global__ void __launch_bounds__(256) wsplit_kernel(const float* __restrict__ Ws1,
                                                     const float* __restrict__ Wn1,
                                                     const float* __restrict__ Ws2,
                                                     const float* __restrict__ Wn2) {
    int idx = blockIdx.x * 256 + threadIdx.x;       // 0 .. 262143
    int L   = idx >> 17;
    int rem = idx & 131071;
    int n   = rem >> 9;
    int kk  = rem & 511;
    const float* W = (L == 0) ? (kk < 256 ? Ws1 : Wn1) : (kk < 256 ? Ws2 : Wn2);
    float v = W[n * 256 + (kk & 255)];
    float hi = tf32f(v);
    g_whi[idx] = hi;
    g_wlo[idx] = tf32f(v - hi);
}

// ---------------- fused tf32x3 mma.sync GEMM + gather-agg + GELU + LN + residual ----------------
// CTA: 64 rows x 256 cols, K=512 (hin k<256; fused agg k>=256). 8 warps = 2(M) x 4(N).
__global__ void __launch_bounds__(256, 2) gemm_ln_mma(
    const float* __restrict__ hin, int L,
    const float* __restrict__ gv, const float* __restrict__ bv,
    const unsigned char* __restrict__ pad,
    float* __restrict__ hout, int zero_pad)
{
    extern __shared__ char sm[];
    float* As_hi = (float*)(sm + OFF_AHI);
    float* As_lo = (float*)(sm + OFF_ALO);
    float* Bs_hi = (float*)(sm + OFF_BHI);
    float* Bs_lo = (float*)(sm + OFF_BLO);
    int*   si    = (int*)(sm + OFF_SI);
    float* sw    = (float*)(sm + OFF_SW);
    float* red1  = (float*)(sm + OFF_R1);
    float* red2  = (float*)(sm + OFF_R2);
    float* sgam  = (float*)(sm + OFF_GAM);
    float* sbet  = (float*)(sm + OFF_BET);
    uint32_t sb  = smem_u32(sm);

    int tid = threadIdx.x;
    int m0 = blockIdx.x * 64;
    int bbase = (m0 >> 11) * NN;
    int wid = tid >> 5, lane = tid & 31;
    int mw = wid >> 2, nw = wid & 3;       // warp grid 2 x 4
    int g = lane >> 2, i = lane & 3;

    for (int e = tid; e < 64 * KNB; e += 256) {
        int r = e / KNB, k = e % KNB;
        si[e] = g_nbr[(size_t)(m0 + r) * KNB + k];
        sw[e] = g_w[(size_t)(m0 + r) * KNB + k];
    }
    sgam[tid] = gv[tid];
    sbet[tid] = bv[tid];

    float acc[2][8][4];
    #pragma unroll
    for (int a = 0; a < 2; a++)
        #pragma unroll
        for (int b = 0; b < 8; b++)
            #pragma unroll
            for (int c = 0; c < 4; c++) acc[a][b][c] = 0.f;

    const float* gwh = g_whi + (size_t)L * 131072;
    const float* gwl = g_wlo + (size_t)L * 131072;

    for (int c = 0; c < 16; ++c) {
        __syncthreads();
        int k0 = (c & 7) * 32;

        // ---- B tiles via cp.async: 256 n-rows x 32 k, hi & lo ----
        #pragma unroll
        for (int t = 0; t < 8; ++t) {
            int fidx = t * 256 + tid;
            int n = fidx >> 3, q4 = fidx & 7;
            uint32_t doff = (uint32_t)((n * PADK + q4 * 4) * 4);
            const float* srch = gwh + (size_t)n * 512 + c * 32 + q4 * 4;
            const float* srcl = gwl + (size_t)n * 512 + c * 32 + q4 * 4;
            cp16(sb + OFF_BHI + doff, srch);
            cp16(sb + OFF_BLO + doff, srcl);
        }
        asm volatile("cp.async.commit_group;" ::: "memory");

        // ---- A tile: 64 rows x 32 k, hi/lo (fused gather-agg for c>=8) ----
        #pragma unroll
        for (int t = 0; t < 2; ++t) {
            int fidx = tid * 2 + t;
            int r = fidx >> 3, q4 = fidx & 7;
            float4 v;
            if (c < 8) {
                v = *(const float4*)(hin + (size_t)(m0 + r) * HH + k0 + q4 * 4);
            } else {
                v = make_float4(0.f, 0.f, 0.f, 0.f);
                #pragma unroll
                for (int j = 0; j < KNB; ++j) {
                    float wj = sw[r * KNB + j];
                    const float4 nv = *(const float4*)(hin +
                        (size_t)(bbase + si[r * KNB + j]) * HH + k0 + q4 * 4);
                    v.x = fmaf(wj, nv.x, v.x);
                    v.y = fmaf(wj, nv.y, v.y);
                    v.z = fmaf(wj, nv.z, v.z);
                    v.w = fmaf(wj, nv.w, v.w);
                }
            }
            float4 hi, lo;
            hi.x = tf32f(v.x); lo.x = tf32f(v.x - hi.x);
            hi.y = tf32f(v.y); lo.y = tf32f(v.y - hi.y);
            hi.z = tf32f(v.z); lo.z = tf32f(v.z - hi.z);
            hi.w = tf32f(v.w); lo.w = tf32f(v.w - hi.w);
            int off = r * PADK + q4 * 4;
            *(float4*)(As_hi + off) = hi;
            *(float4*)(As_lo + off) = lo;
        }
        asm volatile("cp.async.wait_all;" ::: "memory");
        __syncthreads();

        // ---- MMA: 4 k8-steps ----
        #pragma unroll
        for (int k8 = 0; k8 < 4; ++k8) {
            int kc = k8 * 8 + i;
            uint32_t ah[2][4], al[2][4];
            #pragma unroll
            for (int fm = 0; fm < 2; ++fm) {
                const float* p = As_hi + (mw * 32 + fm * 16 + g) * PADK + kc;
                const float* q = As_lo + (mw * 32 + fm * 16 + g) * PADK + kc;
                ah[fm][0] = __float_as_uint(p[0]);
                ah[fm][1] = __float_as_uint(p[8 * PADK]);
                ah[fm][2] = __float_as_uint(p[4]);
                ah[fm][3] = __float_as_uint(p[8 * PADK + 4]);
                al[fm][0] = __float_as_uint(q[0]);
                al[fm][1] = __float_as_uint(q[8 * PADK]);
                al[fm][2] = __float_as_uint(q[4]);
                al[fm][3] = __float_as_uint(q[8 * PADK + 4]);
            }
            #pragma unroll
            for (int fn = 0; fn < 8; ++fn) {
                const float* pb = Bs_hi + (nw * 64 + fn * 8 + g) * PADK + kc;
                const float* ql = Bs_lo + (nw * 64 + fn * 8 + g) * PADK + kc;
                uint32_t bh0 = __float_as_uint(pb[0]);
                uint32_t bh1 = __float_as_uint(pb[4]);
                uint32_t bl0 = __float_as_uint(ql[0]);
                uint32_t bl1 = __float_as_uint(ql[4]);
                #pragma unroll
                for (int fm = 0; fm < 2; ++fm) {
                    mma8(acc[fm][fn], ah[fm][0], ah[fm][1], ah[fm][2], ah[fm][3], bh0, bh1);
                    mma8(acc[fm][fn], ah[fm][0], ah[fm][1], ah[fm][2], ah[fm][3], bl0, bl1);
                    mma8(acc[fm][fn], al[fm][0], al[fm][1], al[fm][2], al[fm][3], bh0, bh1);
                }
            }
        }
    }
    __syncthreads();

    // ---- epilogue: GELU -> LN stats -> normalize + residual + store ----
    float s1[4] = {0.f, 0.f, 0.f, 0.f};
    float s2[4] = {0.f, 0.f, 0.f, 0.f};
    #pragma unroll
    for (int fm = 0; fm < 2; ++fm)
        #pragma unroll
        for (int fn = 0; fn < 8; ++fn)
            #pragma unroll
            for (int cc = 0; cc < 4; ++cc) {
                float x = acc[fm][fn][cc];
                float gl = 0.5f * x * (1.0f + erff(x * 0.70710678118654752f));
                acc[fm][fn][cc] = gl;
                int rs = fm * 2 + (cc >> 1);
                s1[rs] += gl;
                s2[rs] = fmaf(gl, gl, s2[rs]);
            }
    #pragma unroll
    for (int rs = 0; rs < 4; ++rs) {
        #pragma unroll
        for (int o = 1; o <= 2; o <<= 1) {
            s1[rs] += __shfl_xor_sync(0xffffffffu, s1[rs], o);
            s2[rs] += __shfl_xor_sync(0xffffffffu, s2[rs], o);
        }
    }
    if (i == 0) {
        #pragma unroll
        for (int rs = 0; rs < 4; ++rs) {
            int row_l = mw * 32 + (rs >> 1) * 16 + g + (rs & 1) * 8;
            red1[row_l * 4 + nw] = s1[rs];
            red2[row_l * 4 + nw] = s2[rs];
        }
    }
    __syncthreads();

    #pragma unroll
    for (int fm = 0; fm < 2; ++fm) {
        #pragma unroll
        for (int rh = 0; rh < 2; ++rh) {
            int row_l = mw * 32 + fm * 16 + g + rh * 8;
            int row_g = m0 + row_l;
            float st  = red1[row_l * 4 + 0] + red1[row_l * 4 + 1]
                      + red1[row_l * 4 + 2] + red1[row_l * 4 + 3];
            float st2 = red2[row_l * 4 + 0] + red2[row_l * 4 + 1]
                      + red2[row_l * 4 + 2] + red2[row_l * 4 + 3];
            float mu   = st * (1.f / HH);
            float var  = fmaf(-mu, mu, st2 * (1.f / HH));
            float rstd = rsqrtf(var + 1e-5f);
            bool pz = (zero_pad != 0) && (pad[row_g] != 0);
            #pragma unroll
            for (int fn = 0; fn < 8; ++fn) {
                int col = nw * 64 + fn * 8 + 2 * i;
                float v0 = acc[fm][fn][rh * 2 + 0];
                float v1 = acc[fm][fn][rh * 2 + 1];
                float2 res = *(const float2*)(hin + (size_t)row_g * HH + col);
                float2 o;
                o.x = pz ? 0.f : res.x + (v0 - mu) * rstd * sgam[col]     + sbet[col];
                o.y = pz ? 0.f : res.y + (v1 - mu) * rstd * sgam[col + 1] + sbet[col + 1];
                *(float2*)(hout + (size_t)row_g * HH + col) = o;
            }
        }
    }
}

// ---------------- launcher ----------------
extern "C" void kernel_launch(void* const* d_in, const int* in_sizes, int n_in,
                              void* d_out, int out_size) {
    const float*         h0   = (const float*)d_in[0];
    const unsigned char* pad  = (const unsigned char*)d_in[1];
    const float*         cent = (const float*)d_in[2];
    const int*           tids = (const int*)d_in[3];
    const float* Ws1 = (const float*)d_in[4];
    const float* Wn1 = (const float*)d_in[5];
    const float* g1  = (const float*)d_in[6];
    const float* b1  = (const float*)d_in[7];
    const float* Ws2 = (const float*)d_in[8];
    const float* Wn2 = (const float*)d_in[9];
    const float* g2  = (const float*)d_in[10];
    const float* b2  = (const float*)d_in[11];
    float* out = (float*)d_out;

    float* h1;
    cudaGetSymbolAddress((void**)&h1, g_h1);

    cudaFuncSetAttribute(gemm_ln_mma, cudaFuncAttributeMaxDynamicSharedMemorySize, SMEM_TOTAL);

    norm_kernel  <<<MM / 8, 256>>>(h0);
    knn_kernel   <<<dim3(NN / 32, BB), 256>>>(cent, pad);
    weight_kernel<<<MM / 8, 256>>>(h0, pad, tids);
    wsplit_kernel<<<1024, 256>>>(Ws1, Wn1, Ws2, Wn2);

    gemm_ln_mma<<<MM / 64, 256, SMEM_TOTAL>>>(h0, 0, g1, b1, pad, h1, 0);
    gemm_ln_mma<<<MM / 64, 256, SMEM_TOTAL>>>(h1, 1, g2, b2, pad, out, 1);
}

// round 8
// speedup vs baseline: 1.2295x; 1.2206x over previous
#include <cuda_runtime.h>
#include <math.h>
#include <stdint.h>

#define BB 8
#define NN 2048
#define HH 256
#define MM (BB*NN)
#define KNB 6
#define INFD 1e9f

// ---------------- device scratch ----------------
__device__ float  g_h1[MM*HH];          // layer-1 output
__device__ float  g_norm[MM];
__device__ int    g_nbr[MM*KNB];
__device__ float  g_dist[MM*KNB];
__device__ float  g_w[MM*KNB];
__device__ float4 g_bf[2*16*4096];      // fragment-ready B: [L][chunk][f] f=nf*128+k8*32+lane

// ---------------- helpers ----------------
__device__ __forceinline__ uint32_t smem_u32(const void* p) {
    uint32_t a;
    asm("{ .reg .u64 t; cvta.to.shared.u64 t, %1; cvt.u32.u64 %0, t; }" : "=r"(a) : "l"(p));
    return a;
}
__device__ __forceinline__ uint32_t tf32r(float x) {
    uint32_t r; asm("cvt.rna.tf32.f32 %0, %1;" : "=r"(r) : "f"(x)); return r;
}
__device__ __forceinline__ float tf32f(float x) { return __uint_as_float(tf32r(x)); }

__device__ __forceinline__ void mma8(float* c, uint32_t a0, uint32_t a1,
                                     uint32_t a2, uint32_t a3,
                                     uint32_t b0, uint32_t b1) {
    asm volatile("mma.sync.aligned.m16n8k8.row.col.f32.tf32.tf32.f32 "
                 "{%0,%1,%2,%3}, {%4,%5,%6,%7}, {%8,%9}, {%0,%1,%2,%3};"
                 : "+f"(c[0]), "+f"(c[1]), "+f"(c[2]), "+f"(c[3])
                 : "r"(a0), "r"(a1), "r"(a2), "r"(a3), "r"(b0), "r"(b1));
}
__device__ __forceinline__ void cp16(uint32_t dst, const void* src) {
    asm volatile("cp.async.ca.shared.global [%0], [%1], 16;" :: "r"(dst), "l"(src) : "memory");
}

// ---------------- SMEM layout for gemm (bytes) ----------------
#define PADK 36
#define OFF_AHI  0
#define OFF_ALO  9216
#define OFF_BF   18432
#define OFF_SI   83968
#define OFF_SW   85504
#define OFF_R1   87040
#define OFF_R2   88064
#define OFF_GAM  89088
#define OFF_BET  90112
#define SMEM_TOTAL 91136

// ---------------- norm + wsplit combo (launch 0) ----------------
// blocks [0,2048): row norms of h0.  blocks [2048,2560): weight pre-split.
__global__ void __launch_bounds__(256) combo_kernel(const float* __restrict__ h,
                                                    const float* __restrict__ Ws1,
                                                    const float* __restrict__ Wn1,
                                                    const float* __restrict__ Ws2,
                                                    const float* __restrict__ Wn2) {
    if (blockIdx.x < 2048) {
        int warp = threadIdx.x >> 5, lane = threadIdx.x & 31;
        int row = blockIdx.x * 8 + warp;
        const float4* p = (const float4*)(h + (size_t)row * HH);
        float4 a = p[lane * 2], b = p[lane * 2 + 1];
        float s = a.x*a.x + a.y*a.y + a.z*a.z + a.w*a.w
                + b.x*b.x + b.y*b.y + b.z*b.z + b.w*b.w;
        #pragma unroll
        for (int o = 16; o; o >>= 1) s += __shfl_xor_sync(0xffffffffu, s, o);
        if (lane == 0) g_norm[row] = sqrtf(s);
    } else {
        // fragment-ready weight split (validated layout):
        // idx = (L*16+c)*4096 + f;  f = nf*128 + k8*32 + lane
        // n = (nf>>3)*64 + (nf&7)*8 + (lane>>2); i = lane&3; ks = (c&7)*32 + k8*8 + i
        // out float4 = (hi(W[n][ks]), hi(W[n][ks+4]), lo(W[n][ks]), lo(W[n][ks+4]))
        int idx = (blockIdx.x - 2048) * 256 + threadIdx.x;   // 0..131071
        int L   = idx >> 16;
        int rem = idx & 65535;
        int c   = rem >> 12;
        int f   = rem & 4095;
        int lane = f & 31;
        int k8   = (f >> 5) & 3;
        int nf   = f >> 7;
        int n  = (nf >> 3) * 64 + (nf & 7) * 8 + (lane >> 2);
        int i  = lane & 3;
        int ks = (c & 7) * 32 + k8 * 8 + i;
        const float* W = (L == 0) ? (c < 8 ? Ws1 : Wn1) : (c < 8 ? Ws2 : Wn2);
        float w0 = W[n * 256 + ks];
        float w1 = W[n * 256 + ks + 4];
        float h0 = tf32f(w0), h1 = tf32f(w1);
        float l0 = tf32f(w0 - h0), l1 = tf32f(w1 - h1);
        g_bf[idx] = make_float4(h0, h1, l0, l1);
    }
}

// ---------------- brute-force kNN (top-6), exact reference ordering (R5-proven) ----------------
__global__ void __launch_bounds__(256) knn_kernel(const float* __restrict__ cent,
                                                  const unsigned char* __restrict__ pad) {
    __shared__ float2 tbl[NN];
    __shared__ float  mk[32 * 64];
    __shared__ int    mi[32 * 64];

    int b = blockIdx.y;
    int tid = threadIdx.x;
    const float* cb = cent + (size_t)b * NN * 2;
    for (int j = tid; j < NN; j += 256) {
        float cx = cb[2 * j], cy = cb[2 * j + 1];
        if (pad[b * NN + j]) { cx = 1e30f; cy = 1e30f; }
        tbl[j] = make_float2(cx, cy);
    }
    __syncthreads();

    int g = tid >> 3, sub = tid & 7;
    int q = blockIdx.x * 32 + g;
    float2 qc = tbl[q];

    float bk[8]; int bi[8];
    #pragma unroll
    for (int t = 0; t < 8; t++) { bk[t] = 3.0e38f; bi[t] = 0x7fffffff; }

    #pragma unroll 4
    for (int it = 0; it < NN / 8; ++it) {
        int j = it * 8 + sub;
        float2 c = tbl[j];
        float dx = __fadd_rn(qc.x, -c.x);
        float dy = __fadd_rn(qc.y, -c.y);
        float key = __fadd_rn(__fmul_rn(dx, dx), __fmul_rn(dy, dy));
        if (key < bk[7]) {
            bk[7] = key; bi[7] = j;
            #pragma unroll
            for (int t = 7; t > 0; --t) {
                if (bk[t] < bk[t - 1]) {
                    float tk = bk[t]; bk[t] = bk[t - 1]; bk[t - 1] = tk;
                    int   ti = bi[t]; bi[t] = bi[t - 1]; bi[t - 1] = ti;
                }
            }
        }
    }

    #pragma unroll
    for (int t = 0; t < 8; t++) {
        mk[g * 64 + sub * 8 + t] = bk[t];
        mi[g * 64 + sub * 8 + t] = bi[t];
    }
    __syncwarp();

    if (sub == 0) {
        float fs[7]; int fi[7];
        #pragma unroll
        for (int t = 0; t < 7; t++) { fs[t] = 3.0e38f; fi[t] = 0x7fffffff; }
        for (int e = 0; e < 64; ++e) {
            float k2 = mk[g * 64 + e];
            int   i  = mi[g * 64 + e];
            float s  = sqrtf(fmaxf(k2, 0.f));
            bool better = (s < fs[6]) || (s == fs[6] && i < fi[6]);
            if (better) {
                fs[6] = s; fi[6] = i;
                #pragma unroll
                for (int t = 6; t > 0; --t) {
                    bool sw = (fs[t] < fs[t - 1]) || (fs[t] == fs[t - 1] && fi[t] < fi[t - 1]);
                    if (sw) {
                        float tk = fs[t]; fs[t] = fs[t - 1]; fs[t - 1] = tk;
                        int   ti = fi[t]; fi[t] = fi[t - 1]; fi[t - 1] = ti;
                    }
                }
            }
        }
        int row = b * NN + q;
        int outk = 0;
        bool skipped = false;
        for (int t = 0; t < 7 && outk < KNB; ++t) {
            if (!skipped && fi[t] == q) { skipped = true; continue; }
            int idx = fi[t];
            float dd = fs[t];
            if (dd >= 5e8f || idx >= NN) { dd = INFD; idx = 0; }
            g_nbr[row * KNB + outk]  = idx;
            g_dist[row * KNB + outk] = dd;
            outk++;
        }
        for (; outk < KNB; ++outk) {
            g_nbr[row * KNB + outk] = 0;
            g_dist[row * KNB + outk] = INFD;
        }
    }
}

// ---------------- edge weights (R5-proven version, single launch) ----------------
__global__ void __launch_bounds__(256) weight_kernel(const float* __restrict__ h,
                                                     const unsigned char* __restrict__ pad,
                                                     const int* __restrict__ tids) {
    int warp = threadIdx.x >> 5, lane = threadIdx.x & 31;
    int row = blockIdx.x * 8 + warp;
    int b = row / NN;

    const float4* hp = (const float4*)(h + (size_t)row * HH);
    float4 qa = hp[lane * 2], qb = hp[lane * 2 + 1];
    float nq = fmaxf(g_norm[row], 1e-12f);

    float invd[6], sim[6]; int nb[6]; bool val[6];
    float sum_inv = 0.f, sum_sim = 0.f;
    #pragma unroll
    for (int k = 0; k < KNB; k++) {
        int idx  = g_nbr[row * KNB + k];
        float dk = g_dist[row * KNB + k];
        int nrow = b * NN + idx;
        const float4* np = (const float4*)(h + (size_t)nrow * HH);
        float4 na = np[lane * 2], nb4 = np[lane * 2 + 1];
        float dot = qa.x*na.x + qa.y*na.y + qa.z*na.z + qa.w*na.w
                  + qb.x*nb4.x + qb.y*nb4.y + qb.z*nb4.z + qb.w*nb4.w;
        #pragma unroll
        for (int o = 16; o; o >>= 1) dot += __shfl_xor_sync(0xffffffffu, dot, o);
        float nn = fmaxf(g_norm[nrow], 1e-12f);
        bool v = dk < 5e8f;
        float s  = v ? fmaxf(dot / (nq * nn), 0.f) : 0.f;
        float id = v ? (1.f / fmaxf(dk, 1e-4f)) : 0.f;
        invd[k] = id; sim[k] = s; nb[k] = idx; val[k] = v;
        sum_inv += id; sum_sim += s;
    }

    if (lane == 0) {
        bool pq = pad[row] != 0;
        int tq = tids[row];
        float rs = 1.f / fmaxf(sum_inv, 1e-8f);
        float rm = 1.f / fmaxf(sum_sim, 1e-8f);
        float w[6]; float tot = 0.f;
        #pragma unroll
        for (int k = 0; k < KNB; k++) {
            float wk = 0.6f * invd[k] * rs + 0.4f * sim[k] * rm;
            int tnb = tids[b * NN + nb[k]];
            if (val[k] && (tq != tnb)) wk *= 1.2f;
            w[k] = wk; tot += wk;
        }
        float rt = 1.f / fmaxf(tot, 1e-8f);
        #pragma unroll
        for (int k = 0; k < KNB; k++)
            g_w[row * KNB + k] = pq ? 0.f : w[k] * rt;
    }
}

// ---------------- fused tf32x3 mma.sync GEMM + gather-agg + GELU + LN + residual ----------------
// CTA: 64 rows x 256 cols, K=512. 8 warps = 2(M) x 4(N). B loads fragment-ready (float4).
__global__ void __launch_bounds__(256, 2) gemm_ln_mma(
    const float* __restrict__ hin, int L,
    const float* __restrict__ gv, const float* __restrict__ bv,
    const unsigned char* __restrict__ pad,
    float* __restrict__ hout, int zero_pad)
{
    extern __shared__ char sm[];
    float* As_hi = (float*)(sm + OFF_AHI);
    float* As_lo = (float*)(sm + OFF_ALO);
    int*   si    = (int*)(sm + OFF_SI);
    float* sw    = (float*)(sm + OFF_SW);
    float* red1  = (float*)(sm + OFF_R1);
    float* red2  = (float*)(sm + OFF_R2);
    float* sgam  = (float*)(sm + OFF_GAM);
    float* sbet  = (float*)(sm + OFF_BET);
    uint32_t sb  = smem_u32(sm);

    int tid = threadIdx.x;
    int m0 = blockIdx.x * 64;
    int bbase = (m0 >> 11) * NN;
    int wid = tid >> 5, lane = tid & 31;
    int mw = wid >> 2, nw = wid & 3;       // warp grid 2 x 4
    int g = lane >> 2, i = lane & 3;

    for (int e = tid; e < 64 * KNB; e += 256) {
        int r = e / KNB, k = e % KNB;
        si[e] = g_nbr[(size_t)(m0 + r) * KNB + k];
        sw[e] = g_w[(size_t)(m0 + r) * KNB + k];
    }
    sgam[tid] = gv[tid];
    sbet[tid] = bv[tid];

    float acc[2][8][4];
    #pragma unroll
    for (int a = 0; a < 2; a++)
        #pragma unroll
        for (int b = 0; b < 8; b++)
            #pragma unroll
            for (int c = 0; c < 4; c++) acc[a][b][c] = 0.f;

    for (int c = 0; c < 16; ++c) {
        __syncthreads();
        int k0 = (c & 7) * 32;

        // ---- B tile via cp.async: fragment-ready float4, 4096 per chunk ----
        const float4* gbf = g_bf + ((size_t)(L * 16 + c) << 12);
        #pragma unroll
        for (int t = 0; t < 16; ++t) {
            int f = t * 256 + tid;
            cp16(sb + OFF_BF + f * 16, gbf + f);
        }
        asm volatile("cp.async.commit_group;" ::: "memory");

        // ---- A tile: 64 rows x 32 k, hi/lo (fused gather-agg for c>=8) ----
        #pragma unroll
        for (int t = 0; t < 2; ++t) {
            int fidx = tid * 2 + t;
            int r = fidx >> 3, q4 = fidx & 7;
            float4 v;
            if (c < 8) {
                v = *(const float4*)(hin + (size_t)(m0 + r) * HH + k0 + q4 * 4);
            } else {
                v = make_float4(0.f, 0.f, 0.f, 0.f);
                #pragma unroll
                for (int j = 0; j < KNB; ++j) {
                    float wj = sw[r * KNB + j];
                    const float4 nv = *(const float4*)(hin +
                        (size_t)(bbase + si[r * KNB + j]) * HH + k0 + q4 * 4);
                    v.x = fmaf(wj, nv.x, v.x);
                    v.y = fmaf(wj, nv.y, v.y);
                    v.z = fmaf(wj, nv.z, v.z);
                    v.w = fmaf(wj, nv.w, v.w);
                }
            }
            float4 hi, lo;
            hi.x = tf32f(v.x); lo.x = tf32f(v.x - hi.x);
            hi.y = tf32f(v.y); lo.y = tf32f(v.y - hi.y);
            hi.z = tf32f(v.z); lo.z = tf32f(v.z - hi.z);
            hi.w = tf32f(v.w); lo.w = tf32f(v.w - hi.w);
            int off = r * PADK + q4 * 4;
            *(float4*)(As_hi + off) = hi;
            *(float4*)(As_lo + off) = lo;
        }
        asm volatile("cp.async.wait_all;" ::: "memory");
        __syncthreads();

        const float4* bf4 = (const float4*)(sm + OFF_BF);

        // ---- MMA: 4 k8-steps ----
        #pragma unroll
        for (int k8 = 0; k8 < 4; ++k8) {
            int kc = k8 * 8 + i;
            uint32_t ah[2][4], al[2][4];
            #pragma unroll
            for (int fm = 0; fm < 2; ++fm) {
                const float* p = As_hi + (mw * 32 + fm * 16 + g) * PADK + kc;
                const float* q = As_lo + (mw * 32 + fm * 16 + g) * PADK + kc;
                ah[fm][0] = __float_as_uint(p[0]);
                ah[fm][1] = __float_as_uint(p[8 * PADK]);
                ah[fm][2] = __float_as_uint(p[4]);
                ah[fm][3] = __float_as_uint(p[8 * PADK + 4]);
                al[fm][0] = __float_as_uint(q[0]);
                al[fm][1] = __float_as_uint(q[8 * PADK]);
                al[fm][2] = __float_as_uint(q[4]);
                al[fm][3] = __float_as_uint(q[8 * PADK + 4]);
            }
            #pragma unroll
            for (int fn = 0; fn < 8; ++fn) {
                float4 B = bf4[((nw * 8 + fn) * 4 + k8) * 32 + lane];
                uint32_t bh0 = __float_as_uint(B.x);
                uint32_t bh1 = __float_as_uint(B.y);
                uint32_t bl0 = __float_as_uint(B.z);
                uint32_t bl1 = __float_as_uint(B.w);
                #pragma unroll
                for (int fm = 0; fm < 2; ++fm) {
                    mma8(acc[fm][fn], ah[fm][0], ah[fm][1], ah[fm][2], ah[fm][3], bh0, bh1);
                    mma8(acc[fm][fn], ah[fm][0], ah[fm][1], ah[fm][2], ah[fm][3], bl0, bl1);
                    mma8(acc[fm][fn], al[fm][0], al[fm][1], al[fm][2], al[fm][3], bh0, bh1);
                }
            }
        }
    }
    __syncthreads();

    // ---- epilogue: GELU -> LN stats -> normalize + residual + store ----
    float s1[4] = {0.f, 0.f, 0.f, 0.f};
    float s2[4] = {0.f, 0.f, 0.f, 0.f};
    #pragma unroll
    for (int fm = 0; fm < 2; ++fm)
        #pragma unroll
        for (int fn = 0; fn < 8; ++fn)
            #pragma unroll
            for (int cc = 0; cc < 4; ++cc) {
                float x = acc[fm][fn][cc];
                float gl = 0.5f * x * (1.0f + erff(x * 0.70710678118654752f));
                acc[fm][fn][cc] = gl;
                int rs = fm * 2 + (cc >> 1);
                s1[rs] += gl;
                s2[rs] = fmaf(gl, gl, s2[rs]);
            }
    #pragma unroll
    for (int rs = 0; rs < 4; ++rs) {
        #pragma unroll
        for (int o = 1; o <= 2; o <<= 1) {
            s1[rs] += __shfl_xor_sync(0xffffffffu, s1[rs], o);
            s2[rs] += __shfl_xor_sync(0xffffffffu, s2[rs], o);
        }
    }
    if (i == 0) {
        #pragma unroll
        for (int rs = 0; rs < 4; ++rs) {
            int row_l = mw * 32 + (rs >> 1) * 16 + g + (rs & 1) * 8;
            red1[row_l * 4 + nw] = s1[rs];
            red2[row_l * 4 + nw] = s2[rs];
        }
    }
    __syncthreads();

    #pragma unroll
    for (int fm = 0; fm < 2; ++fm) {
        #pragma unroll
        for (int rh = 0; rh < 2; ++rh) {
            int row_l = mw * 32 + fm * 16 + g + rh * 8;
            int row_g = m0 + row_l;
            float st  = red1[row_l * 4 + 0] + red1[row_l * 4 + 1]
                      + red1[row_l * 4 + 2] + red1[row_l * 4 + 3];
            float st2 = red2[row_l * 4 + 0] + red2[row_l * 4 + 1]
                      + red2[row_l * 4 + 2] + red2[row_l * 4 + 3];
            float mu   = st * (1.f / HH);
            float var  = fmaf(-mu, mu, st2 * (1.f / HH));
            float rstd = rsqrtf(var + 1e-5f);
            bool pz = (zero_pad != 0) && (pad[row_g] != 0);
            #pragma unroll
            for (int fn = 0; fn < 8; ++fn) {
                int col = nw * 64 + fn * 8 + 2 * i;
                float v0 = acc[fm][fn][rh * 2 + 0];
                float v1 = acc[fm][fn][rh * 2 + 1];
                float2 res = *(const float2*)(hin + (size_t)row_g * HH + col);
                float2 o;
                o.x = pz ? 0.f : res.x + (v0 - mu) * rstd * sgam[col]     + sbet[col];
                o.y = pz ? 0.f : res.y + (v1 - mu) * rstd * sgam[col + 1] + sbet[col + 1];
                *(float2*)(hout + (size_t)row_g * HH + col) = o;
            }
        }
    }
}

// ---------------- launcher ----------------
extern "C" void kernel_launch(void* const* d_in, const int* in_sizes, int n_in,
                              void* d_out, int out_size) {
    const float*         h0   = (const float*)d_in[0];
    const unsigned char* pad  = (const unsigned char*)d_in[1];
    const float*         cent = (const float*)d_in[2];
    const int*           tids = (const int*)d_in[3];
    const float* Ws1 = (const float*)d_in[4];
    const float* Wn1 = (const float*)d_in[5];
    const float* g1  = (const float*)d_in[6];
    const float* b1  = (const float*)d_in[7];
    const float* Ws2 = (const float*)d_in[8];
    const float* Wn2 = (const float*)d_in[9];
    const float* g2  = (const float*)d_in[10];
    const float* b2  = (const float*)d_in[11];
    float* out = (float*)d_out;

    float* h1;
    cudaGetSymbolAddress((void**)&h1, g_h1);

    cudaFuncSetAttribute(gemm_ln_mma, cudaFuncAttributeMaxDynamicSharedMemorySize, SMEM_TOTAL);

    combo_kernel <<<2560, 256>>>(h0, Ws1, Wn1, Ws2, Wn2);     // 0: norms + wsplit
    knn_kernel   <<<dim3(NN / 32, BB), 256>>>(cent, pad);     // 1
    weight_kernel<<<MM / 8, 256>>>(h0, pad, tids);            // 2
    gemm_ln_mma<<<MM / 64, 256, SMEM_TOTAL>>>(h0, 0, g1, b1, pad, h1, 0);   // 3 (profiled)
    gemm_ln_mma<<<MM / 64, 256, SMEM_TOTAL>>>(h1, 1, g2, b2, pad, out, 1);  // 4
}

// round 9
// speedup vs baseline: 1.3697x; 1.1141x over previous
#include <cuda_runtime.h>
#include <cuda_bf16.h>
#include <math.h>
#include <stdint.h>

#define BB 8
#define NN 2048
#define HH 256
#define MM (BB*NN)
#define KNB 6
#define INFD 1e9f

// ---------------- device scratch ----------------
__device__ float g_h1[MM*HH];
__device__ float g_agg[MM*HH];
__device__ float g_norm[MM];
__device__ int   g_nbr[MM*KNB];
__device__ float g_dist[MM*KNB];
__device__ float g_w[MM*KNB];
__device__ uint4 g_bf[2*16*2*32*32];   // fragment-ready bf16 B: [L][c][kg][nf][lane]

// ---------------- helpers ----------------
__device__ __forceinline__ uint32_t smem_u32(const void* p) {
    uint32_t a;
    asm("{ .reg .u64 t; cvta.to.shared.u64 t, %1; cvt.u32.u64 %0, t; }" : "=r"(a) : "l"(p));
    return a;
}
__device__ __forceinline__ void bfsplit2(float x, float y, uint32_t& hi, uint32_t& lo) {
    __nv_bfloat16 xh = __float2bfloat16(x), yh = __float2bfloat16(y);
    float xr = x - __bfloat162float(xh);
    float yr = y - __bfloat162float(yh);
    __nv_bfloat16 xl = __float2bfloat16(xr), yl = __float2bfloat16(yr);
    uint16_t xhb = *(uint16_t*)&xh, yhb = *(uint16_t*)&yh;
    uint16_t xlb = *(uint16_t*)&xl, ylb = *(uint16_t*)&yl;
    hi = (uint32_t)xhb | ((uint32_t)yhb << 16);
    lo = (uint32_t)xlb | ((uint32_t)ylb << 16);
}
__device__ __forceinline__ void mma16(float* c, uint32_t a0, uint32_t a1,
                                      uint32_t a2, uint32_t a3,
                                      uint32_t b0, uint32_t b1) {
    asm volatile("mma.sync.aligned.m16n8k16.row.col.f32.bf16.bf16.f32 "
                 "{%0,%1,%2,%3}, {%4,%5,%6,%7}, {%8,%9}, {%0,%1,%2,%3};"
                 : "+f"(c[0]), "+f"(c[1]), "+f"(c[2]), "+f"(c[3])
                 : "r"(a0), "r"(a1), "r"(a2), "r"(a3), "r"(b0), "r"(b1));
}
__device__ __forceinline__ void cp16(uint32_t dst, const void* src) {
    asm volatile("cp.async.ca.shared.global [%0], [%1], 16;" :: "r"(dst), "l"(src) : "memory");
}

// ---------------- SMEM layout for gemm (bytes) ----------------
#define PADP 20                 // uint2 per A row (16 data + 4 pad)
#define OFF_A0   0              // 64*20*8 = 10240
#define OFF_A1   10240
#define OFF_B0   20480          // 2*32*32*16 = 32768
#define OFF_B1   53248
#define OFF_GAM  86016
#define OFF_BET  87040
#define OFF_R1   88064
#define OFF_R2   89088
#define SMEM_TOTAL 90112

// ---------------- combo: row norms + fragment-ready bf16 weight split ----------------
__global__ void __launch_bounds__(256) combo_kernel(const float* __restrict__ h,
                                                    const float* __restrict__ Ws1,
                                                    const float* __restrict__ Wn1,
                                                    const float* __restrict__ Ws2,
                                                    const float* __restrict__ Wn2) {
    if (blockIdx.x < 2048) {
        int warp = threadIdx.x >> 5, lane = threadIdx.x & 31;
        int row = blockIdx.x * 8 + warp;
        const float4* p = (const float4*)(h + (size_t)row * HH);
        float4 a = p[lane * 2], b = p[lane * 2 + 1];
        float s = a.x*a.x + a.y*a.y + a.z*a.z + a.w*a.w
                + b.x*b.x + b.y*b.y + b.z*b.z + b.w*b.w;
        #pragma unroll
        for (int o = 16; o; o >>= 1) s += __shfl_xor_sync(0xffffffffu, s, o);
        if (lane == 0) g_norm[row] = sqrtf(s);
    } else {
        // B fragment: per (L,c,kg,nf,lane): n = nf*8 + (lane>>2), i = lane&3
        // b0 covers k = ks+2i, ks+2i+1; b1 covers ks+2i+8, ks+2i+9; ks = (c&7)*32 + kg*16
        int idx = (blockIdx.x - 2048) * 256 + threadIdx.x;   // 0..65535
        int lane = idx & 31;
        int nf   = (idx >> 5) & 31;
        int kg   = (idx >> 10) & 1;
        int c    = (idx >> 11) & 15;
        int L    = idx >> 15;
        int g = lane >> 2, i = lane & 3;
        int n  = nf * 8 + g;
        int ks = (c & 7) * 32 + kg * 16;
        const float* W = (L == 0) ? (c < 8 ? Ws1 : Wn1) : (c < 8 ? Ws2 : Wn2);
        float w00 = W[n * 256 + ks + 2 * i];
        float w01 = W[n * 256 + ks + 2 * i + 1];
        float w10 = W[n * 256 + ks + 2 * i + 8];
        float w11 = W[n * 256 + ks + 2 * i + 9];
        uint32_t b0h, b0l, b1h, b1l;
        bfsplit2(w00, w01, b0h, b0l);
        bfsplit2(w10, w11, b1h, b1l);
        uint4 o; o.x = b0h; o.y = b1h; o.z = b0l; o.w = b1l;
        g_bf[idx] = o;
    }
}

// ---------------- brute-force kNN (top-6), R5-proven ----------------
__global__ void __launch_bounds__(256) knn_kernel(const float* __restrict__ cent,
                                                  const unsigned char* __restrict__ pad) {
    __shared__ float2 tbl[NN];
    __shared__ float  mk[32 * 64];
    __shared__ int    mi[32 * 64];

    int b = blockIdx.y;
    int tid = threadIdx.x;
    const float* cb = cent + (size_t)b * NN * 2;
    for (int j = tid; j < NN; j += 256) {
        float cx = cb[2 * j], cy = cb[2 * j + 1];
        if (pad[b * NN + j]) { cx = 1e30f; cy = 1e30f; }
        tbl[j] = make_float2(cx, cy);
    }
    __syncthreads();

    int g = tid >> 3, sub = tid & 7;
    int q = blockIdx.x * 32 + g;
    float2 qc = tbl[q];

    float bk[8]; int bi[8];
    #pragma unroll
    for (int t = 0; t < 8; t++) { bk[t] = 3.0e38f; bi[t] = 0x7fffffff; }

    #pragma unroll 4
    for (int it = 0; it < NN / 8; ++it) {
        int j = it * 8 + sub;
        float2 c = tbl[j];
        float dx = __fadd_rn(qc.x, -c.x);
        float dy = __fadd_rn(qc.y, -c.y);
        float key = __fadd_rn(__fmul_rn(dx, dx), __fmul_rn(dy, dy));
        if (key < bk[7]) {
            bk[7] = key; bi[7] = j;
            #pragma unroll
            for (int t = 7; t > 0; --t) {
                if (bk[t] < bk[t - 1]) {
                    float tk = bk[t]; bk[t] = bk[t - 1]; bk[t - 1] = tk;
                    int   ti = bi[t]; bi[t] = bi[t - 1]; bi[t - 1] = ti;
                }
            }
        }
    }

    #pragma unroll
    for (int t = 0; t < 8; t++) {
        mk[g * 64 + sub * 8 + t] = bk[t];
        mi[g * 64 + sub * 8 + t] = bi[t];
    }
    __syncwarp();

    if (sub == 0) {
        float fs[7]; int fi[7];
        #pragma unroll
        for (int t = 0; t < 7; t++) { fs[t] = 3.0e38f; fi[t] = 0x7fffffff; }
        for (int e = 0; e < 64; ++e) {
            float k2 = mk[g * 64 + e];
            int   i  = mi[g * 64 + e];
            float s  = sqrtf(fmaxf(k2, 0.f));
            bool better = (s < fs[6]) || (s == fs[6] && i < fi[6]);
            if (better) {
                fs[6] = s; fi[6] = i;
                #pragma unroll
                for (int t = 6; t > 0; --t) {
                    bool sw = (fs[t] < fs[t - 1]) || (fs[t] == fs[t - 1] && fi[t] < fi[t - 1]);
                    if (sw) {
                        float tk = fs[t]; fs[t] = fs[t - 1]; fs[t - 1] = tk;
                        int   ti = fi[t]; fi[t] = fi[t - 1]; fi[t - 1] = ti;
                    }
                }
            }
        }
        int row = b * NN + q;
        int outk = 0;
        bool skipped = false;
        for (int t = 0; t < 7 && outk < KNB; ++t) {
            if (!skipped && fi[t] == q) { skipped = true; continue; }
            int idx = fi[t];
            float dd = fs[t];
            if (dd >= 5e8f || idx >= NN) { dd = INFD; idx = 0; }
            g_nbr[row * KNB + outk]  = idx;
            g_dist[row * KNB + outk] = dd;
            outk++;
        }
        for (; outk < KNB; ++outk) {
            g_nbr[row * KNB + outk] = 0;
            g_dist[row * KNB + outk] = INFD;
        }
    }
}

// ---------------- edge weights + fused layer-1 aggregation ----------------
__global__ void __launch_bounds__(256) weight_agg_kernel(const float* __restrict__ h,
                                                         const unsigned char* __restrict__ pad,
                                                         const int* __restrict__ tids) {
    int warp = threadIdx.x >> 5, lane = threadIdx.x & 31;
    int row = blockIdx.x * 8 + warp;
    int b = row / NN;

    const float4* hp = (const float4*)(h + (size_t)row * HH);
    float4 qa = hp[lane * 2], qb = hp[lane * 2 + 1];
    float nq = fmaxf(g_norm[row], 1e-12f);

    float invd[6], sim[6]; int nb[6]; bool val[6];
    float sum_inv = 0.f, sum_sim = 0.f;
    #pragma unroll
    for (int k = 0; k < KNB; k++) {
        int idx  = g_nbr[row * KNB + k];
        float dk = g_dist[row * KNB + k];
        int nrow = b * NN + idx;
        const float4* np = (const float4*)(h + (size_t)nrow * HH);
        float4 na = np[lane * 2], nb4 = np[lane * 2 + 1];
        float dot = qa.x*na.x + qa.y*na.y + qa.z*na.z + qa.w*na.w
                  + qb.x*nb4.x + qb.y*nb4.y + qb.z*nb4.z + qb.w*nb4.w;
        #pragma unroll
        for (int o = 16; o; o >>= 1) dot += __shfl_xor_sync(0xffffffffu, dot, o);
        float nn = fmaxf(g_norm[nrow], 1e-12f);
        bool v = dk < 5e8f;
        float s  = v ? fmaxf(dot / (nq * nn), 0.f) : 0.f;
        float id = v ? (1.f / fmaxf(dk, 1e-4f)) : 0.f;
        invd[k] = id; sim[k] = s; nb[k] = idx; val[k] = v;
        sum_inv += id; sum_sim += s;
    }

    // all lanes compute final weights (inputs are warp-uniform)
    bool pq = pad[row] != 0;
    int tq = tids[row];
    float rs = 1.f / fmaxf(sum_inv, 1e-8f);
    float rm = 1.f / fmaxf(sum_sim, 1e-8f);
    float w[6]; float tot = 0.f;
    #pragma unroll
    for (int k = 0; k < KNB; k++) {
        float wk = 0.6f * invd[k] * rs + 0.4f * sim[k] * rm;
        int tnb = tids[b * NN + nb[k]];
        if (val[k] && (tq != tnb)) wk *= 1.2f;
        w[k] = wk; tot += wk;
    }
    float rt = 1.f / fmaxf(tot, 1e-8f);
    float wf[6];
    #pragma unroll
    for (int k = 0; k < KNB; k++) wf[k] = pq ? 0.f : w[k] * rt;
    if (lane == 0) {
        #pragma unroll
        for (int k = 0; k < KNB; k++) g_w[row * KNB + k] = wf[k];
    }

    // fused layer-1 aggregation: rows are L1-hot from the dot pass
    float4 A0 = make_float4(0.f, 0.f, 0.f, 0.f);
    float4 A1 = make_float4(0.f, 0.f, 0.f, 0.f);
    #pragma unroll
    for (int k = 0; k < KNB; k++) {
        const float4* np = (const float4*)(h + (size_t)(b * NN + nb[k]) * HH);
        float4 na = np[lane * 2], nb4 = np[lane * 2 + 1];
        float wk = wf[k];
        A0.x = fmaf(wk, na.x, A0.x);  A0.y = fmaf(wk, na.y, A0.y);
        A0.z = fmaf(wk, na.z, A0.z);  A0.w = fmaf(wk, na.w, A0.w);
        A1.x = fmaf(wk, nb4.x, A1.x); A1.y = fmaf(wk, nb4.y, A1.y);
        A1.z = fmaf(wk, nb4.z, A1.z); A1.w = fmaf(wk, nb4.w, A1.w);
    }
    float4* op = (float4*)(g_agg + (size_t)row * HH);
    op[lane * 2]     = A0;
    op[lane * 2 + 1] = A1;
}

// ---------------- layer-2 aggregation (R2-proven) ----------------
__global__ void __launch_bounds__(256) agg_kernel(const float* __restrict__ h) {
    int row = blockIdx.x;
    int b = row >> 11;
    __shared__ float sw[KNB];
    __shared__ int   si[KNB];
    int t = threadIdx.x;
    if (t < KNB) { sw[t] = g_w[row * KNB + t]; si[t] = g_nbr[row * KNB + t]; }
    __syncthreads();
    float a = 0.f;
    #pragma unroll
    for (int k = 0; k < KNB; k++)
        a = fmaf(sw[k], h[((size_t)(b * NN + si[k])) * HH + t], a);
    g_agg[(size_t)row * HH + t] = a;
}

// ---------------- fused bf16x3 mma GEMM + GELU + LN + residual ----------------
// CTA: 64 rows x 256 cols, K=512 (hin k<256 ; g_agg k>=256). 8 warps = 2(M) x 4(N).
// Double-buffered A (regs->smem) and B (cp.async), one sync per chunk.
__global__ void __launch_bounds__(256, 2) gemm_ln_mma(
    const float* __restrict__ hin, int L,
    const float* __restrict__ gv, const float* __restrict__ bv,
    const unsigned char* __restrict__ pad,
    float* __restrict__ hout, int zero_pad)
{
    extern __shared__ char sm[];
    float* red1  = (float*)(sm + OFF_R1);
    float* red2  = (float*)(sm + OFF_R2);
    float* sgam  = (float*)(sm + OFF_GAM);
    float* sbet  = (float*)(sm + OFF_BET);
    uint32_t sb  = smem_u32(sm);

    int tid = threadIdx.x;
    int m0 = blockIdx.x * 64;
    int wid = tid >> 5, lane = tid & 31;
    int mw = wid >> 2, nw = wid & 3;       // warp grid 2(M) x 4(N)
    int g = lane >> 2, i = lane & 3;

    sgam[tid] = gv[tid];
    sbet[tid] = bv[tid];

    float acc[2][8][4];
    #pragma unroll
    for (int a = 0; a < 2; a++)
        #pragma unroll
        for (int b2 = 0; b2 < 8; b2++)
            #pragma unroll
            for (int c2 = 0; c2 < 4; c2++) acc[a][b2][c2] = 0.f;

    const uint4* gbfL = g_bf + (size_t)L * 16 * 2048;
    int ar = tid >> 2;              // A row this thread stages
    int kq = (tid & 3) * 8;         // k offset (8 floats) within chunk

    // ---- prologue: prefetch A(0) into regs, launch B(0) ----
    float4 pv0, pv1;
    {
        const float* src = hin + (size_t)(m0 + ar) * HH + kq;
        pv0 = *(const float4*)src;
        pv1 = *(const float4*)(src + 4);
        #pragma unroll
        for (int t = 0; t < 8; ++t) {
            int f = t * 256 + tid;
            cp16(sb + OFF_B0 + f * 16, gbfL + f);
        }
        asm volatile("cp.async.commit_group;" ::: "memory");
    }

    #pragma unroll 1
    for (int c = 0; c < 16; ++c) {
        int cur = c & 1;
        uint32_t aoff = cur ? OFF_A1 : OFF_A0;
        uint32_t boff = cur ? OFF_B1 : OFF_B0;

        // ---- STS A(c) from prefetched regs (bf16 hi/lo pairs) ----
        {
            uint32_t h0, l0, h1, l1, h2, l2, h3, l3;
            bfsplit2(pv0.x, pv0.y, h0, l0);
            bfsplit2(pv0.z, pv0.w, h1, l1);
            bfsplit2(pv1.x, pv1.y, h2, l2);
            bfsplit2(pv1.z, pv1.w, h3, l3);
            uint4* dst = (uint4*)(sm + aoff + (ar * PADP + (tid & 3) * 4) * 8);
            uint4 u0; u0.x = h0; u0.y = l0; u0.z = h1; u0.w = l1;
            uint4 u1; u1.x = h2; u1.y = l2; u1.z = h3; u1.w = l3;
            dst[0] = u0;
            dst[1] = u1;
        }
        // ---- B(c) arrived? ----
        asm volatile("cp.async.wait_group 0;" ::: "memory");
        __syncthreads();

        // ---- launch B(c+1), prefetch A(c+1) into regs (flies during mma) ----
        if (c < 15) {
            int cn = c + 1;
            const uint4* gsrc = gbfL + (size_t)cn * 2048;
            uint32_t bno = (cn & 1) ? OFF_B1 : OFF_B0;
            #pragma unroll
            for (int t = 0; t < 8; ++t) {
                int f = t * 256 + tid;
                cp16(sb + bno + f * 16, gsrc + f);
            }
            asm volatile("cp.async.commit_group;" ::: "memory");
            const float* asrc = (cn < 8 ? hin : g_agg)
                              + (size_t)(m0 + ar) * HH + (cn & 7) * 32 + kq;
            pv0 = *(const float4*)asrc;
            pv1 = *(const float4*)(asrc + 4);
        }

        // ---- MMA on buffers (cur) ----
        const uint2* Ab = (const uint2*)(sm + aoff);
        const uint4* Bb = (const uint4*)(sm + boff);
        #pragma unroll
        for (int kg = 0; kg < 2; ++kg) {
            uint32_t ah[2][4], al[2][4];
            #pragma unroll
            for (int fm = 0; fm < 2; ++fm) {
                int ro = (mw * 32 + fm * 16 + g) * PADP + kg * 8 + i;
                uint2 x0 = Ab[ro];
                uint2 x1 = Ab[ro + 8 * PADP];
                uint2 x2 = Ab[ro + 4];
                uint2 x3 = Ab[ro + 8 * PADP + 4];
                ah[fm][0] = x0.x; ah[fm][1] = x1.x; ah[fm][2] = x2.x; ah[fm][3] = x3.x;
                al[fm][0] = x0.y; al[fm][1] = x1.y; al[fm][2] = x2.y; al[fm][3] = x3.y;
            }
            #pragma unroll
            for (int fn = 0; fn < 8; ++fn) {
                uint4 B = Bb[(kg * 32 + nw * 8 + fn) * 32 + lane];
                #pragma unroll
                for (int fm = 0; fm < 2; ++fm)
                    mma16(acc[fm][fn], ah[fm][0], ah[fm][1], ah[fm][2], ah[fm][3], B.x, B.y);
                #pragma unroll
                for (int fm = 0; fm < 2; ++fm)
                    mma16(acc[fm][fn], ah[fm][0], ah[fm][1], ah[fm][2], ah[fm][3], B.z, B.w);
                #pragma unroll
                for (int fm = 0; fm < 2; ++fm)
                    mma16(acc[fm][fn], al[fm][0], al[fm][1], al[fm][2], al[fm][3], B.x, B.y);
            }
        }
    }
    __syncthreads();

    // ---- epilogue: GELU -> LN stats -> normalize + residual + store ----
    float s1[4] = {0.f, 0.f, 0.f, 0.f};
    float s2[4] = {0.f, 0.f, 0.f, 0.f};
    #pragma unroll
    for (int fm = 0; fm < 2; ++fm)
        #pragma unroll
        for (int fn = 0; fn < 8; ++fn)
            #pragma unroll
            for (int cc = 0; cc < 4; ++cc) {
                float x = acc[fm][fn][cc];
                float gl = 0.5f * x * (1.0f + erff(x * 0.70710678118654752f));
                acc[fm][fn][cc] = gl;
                int rs = fm * 2 + (cc >> 1);
                s1[rs] += gl;
                s2[rs] = fmaf(gl, gl, s2[rs]);
            }
    #pragma unroll
    for (int rs = 0; rs < 4; ++rs) {
        #pragma unroll
        for (int o = 1; o <= 2; o <<= 1) {
            s1[rs] += __shfl_xor_sync(0xffffffffu, s1[rs], o);
            s2[rs] += __shfl_xor_sync(0xffffffffu, s2[rs], o);
        }
    }
    if (i == 0) {
        #pragma unroll
        for (int rs = 0; rs < 4; ++rs) {
            int row_l = mw * 32 + (rs >> 1) * 16 + g + (rs & 1) * 8;
            red1[row_l * 4 + nw] = s1[rs];
            red2[row_l * 4 + nw] = s2[rs];
        }
    }
    __syncthreads();

    #pragma unroll
    for (int fm = 0; fm < 2; ++fm) {
        #pragma unroll
        for (int rh = 0; rh < 2; ++rh) {
            int row_l = mw * 32 + fm * 16 + g + rh * 8;
            int row_g = m0 + row_l;
            float st  = red1[row_l * 4 + 0] + red1[row_l * 4 + 1]
                      + red1[row_l * 4 + 2] + red1[row_l * 4 + 3];
            float st2 = red2[row_l * 4 + 0] + red2[row_l * 4 + 1]
                      + red2[row_l * 4 + 2] + red2[row_l * 4 + 3];
            float mu   = st * (1.f / HH);
            float var  = fmaf(-mu, mu, st2 * (1.f / HH));
            float rstd = rsqrtf(var + 1e-5f);
            bool pz = (zero_pad != 0) && (pad[row_g] != 0);
            #pragma unroll
            for (int fn = 0; fn < 8; ++fn) {
                int col = nw * 64 + fn * 8 + 2 * i;
                float v0 = acc[fm][fn][rh * 2 + 0];
                float v1 = acc[fm][fn][rh * 2 + 1];
                float2 res = *(const float2*)(hin + (size_t)row_g * HH + col);
                float2 o;
                o.x = pz ? 0.f : res.x + (v0 - mu) * rstd * sgam[col]     + sbet[col];
                o.y = pz ? 0.f : res.y + (v1 - mu) * rstd * sgam[col + 1] + sbet[col + 1];
                *(float2*)(hout + (size_t)row_g * HH + col) = o;
            }
        }
    }
}

// ---------------- launcher ----------------
extern "C" void kernel_launch(void* const* d_in, const int* in_sizes, int n_in,
                              void* d_out, int out_size) {
    const float*         h0   = (const float*)d_in[0];
    const unsigned char* pad  = (const unsigned char*)d_in[1];
    const float*         cent = (const float*)d_in[2];
    const int*           tids = (const int*)d_in[3];
    const float* Ws1 = (const float*)d_in[4];
    const float* Wn1 = (const float*)d_in[5];
    const float* g1  = (const float*)d_in[6];
    const float* b1  = (const float*)d_in[7];
    const float* Ws2 = (const float*)d_in[8];
    const float* Wn2 = (const float*)d_in[9];
    const float* g2  = (const float*)d_in[10];
    const float* b2  = (const float*)d_in[11];
    float* out = (float*)d_out;

    float* h1;
    cudaGetSymbolAddress((void**)&h1, g_h1);

    cudaFuncSetAttribute(gemm_ln_mma, cudaFuncAttributeMaxDynamicSharedMemorySize, SMEM_TOTAL);

    combo_kernel    <<<2304, 256>>>(h0, Ws1, Wn1, Ws2, Wn2);   // 0: norms + bf16 wsplit
    knn_kernel      <<<dim3(NN / 32, BB), 256>>>(cent, pad);   // 1
    weight_agg_kernel<<<MM / 8, 256>>>(h0, pad, tids);         // 2: weights + agg(layer1)
    gemm_ln_mma<<<MM / 64, 256, SMEM_TOTAL>>>(h0, 0, g1, b1, pad, h1, 0);   // 3
    agg_kernel      <<<MM, 256>>>(h1);                         // 4: agg(layer2)
    gemm_ln_mma<<<MM / 64, 256, SMEM_TOTAL>>>(h1, 1, g2, b2, pad, out, 1);  // 5
}

// round 10
// speedup vs baseline: 1.8418x; 1.3446x over previous
#include <cuda_runtime.h>
#include <cuda_bf16.h>
#include <math.h>
#include <stdint.h>

#define BB 8
#define NN 2048
#define HH 256
#define MM (BB*NN)
#define KNB 6
#define INFD 1e9f
typedef unsigned long long u64;

// ---------------- device scratch ----------------
__device__ float  g_h1[MM*HH];
__device__ float  g_agg[MM*HH];
__device__ float  g_norm[MM];
__device__ int    g_nbr[MM*KNB];
__device__ float  g_dist[MM*KNB];
__device__ float  g_w[MM*KNB];
__device__ uint4  g_bf[2*16*2*32*32];   // fragment-ready bf16 B
__device__ float2 g_spts[BB*NN];        // cell-sorted points
__device__ int    g_sidx[BB*NN];        // original per-batch indices
__device__ int    g_cstart[BB*257];     // cell start offsets

// ---------------- helpers ----------------
__device__ __forceinline__ uint32_t smem_u32(const void* p) {
    uint32_t a;
    asm("{ .reg .u64 t; cvta.to.shared.u64 t, %1; cvt.u32.u64 %0, t; }" : "=r"(a) : "l"(p));
    return a;
}
__device__ __forceinline__ void bfsplit2(float x, float y, uint32_t& hi, uint32_t& lo) {
    __nv_bfloat16 xh = __float2bfloat16(x), yh = __float2bfloat16(y);
    float xr = x - __bfloat162float(xh);
    float yr = y - __bfloat162float(yh);
    __nv_bfloat16 xl = __float2bfloat16(xr), yl = __float2bfloat16(yr);
    uint16_t xhb = *(uint16_t*)&xh, yhb = *(uint16_t*)&yh;
    uint16_t xlb = *(uint16_t*)&xl, ylb = *(uint16_t*)&yl;
    hi = (uint32_t)xhb | ((uint32_t)yhb << 16);
    lo = (uint32_t)xlb | ((uint32_t)ylb << 16);
}
__device__ __forceinline__ void mma16(float* c, uint32_t a0, uint32_t a1,
                                      uint32_t a2, uint32_t a3,
                                      uint32_t b0, uint32_t b1) {
    asm volatile("mma.sync.aligned.m16n8k16.row.col.f32.bf16.bf16.f32 "
                 "{%0,%1,%2,%3}, {%4,%5,%6,%7}, {%8,%9}, {%0,%1,%2,%3};"
                 : "+f"(c[0]), "+f"(c[1]), "+f"(c[2]), "+f"(c[3])
                 : "r"(a0), "r"(a1), "r"(a2), "r"(a3), "r"(b0), "r"(b1));
}
__device__ __forceinline__ void cp16(uint32_t dst, const void* src) {
    asm volatile("cp.async.ca.shared.global [%0], [%1], 16;" :: "r"(dst), "l"(src) : "memory");
}

// ---------------- SMEM layout for gemm (bytes) ----------------
#define PADP 20
#define OFF_A0   0
#define OFF_A1   10240
#define OFF_B0   20480
#define OFF_B1   53248
#define OFF_GAM  86016
#define OFF_BET  87040
#define OFF_R1   88064
#define OFF_R2   89088
#define SMEM_TOTAL 90112

// ---------------- combo: norms + bf16 wsplit + spatial binning ----------------
// blocks [0,2048): row norms; [2048,2304): weight split; [2304,2312): per-batch binning
__global__ void __launch_bounds__(256) combo_kernel(const float* __restrict__ h,
                                                    const float* __restrict__ Ws1,
                                                    const float* __restrict__ Wn1,
                                                    const float* __restrict__ Ws2,
                                                    const float* __restrict__ Wn2,
                                                    const float* __restrict__ cent,
                                                    const unsigned char* __restrict__ pad) {
    __shared__ int cnt[257];
    __shared__ int cbase[257];
    int bx = blockIdx.x;
    int tid = threadIdx.x;
    if (bx < 2048) {
        int warp = tid >> 5, lane = tid & 31;
        int row = bx * 8 + warp;
        const float4* p = (const float4*)(h + (size_t)row * HH);
        float4 a = p[lane * 2], b = p[lane * 2 + 1];
        float s = a.x*a.x + a.y*a.y + a.z*a.z + a.w*a.w
                + b.x*b.x + b.y*b.y + b.z*b.z + b.w*b.w;
        #pragma unroll
        for (int o = 16; o; o >>= 1) s += __shfl_xor_sync(0xffffffffu, s, o);
        if (lane == 0) g_norm[row] = sqrtf(s);
    } else if (bx < 2304) {
        int idx = (bx - 2048) * 256 + tid;   // 0..65535
        int lane = idx & 31;
        int nf   = (idx >> 5) & 31;
        int kg   = (idx >> 10) & 1;
        int c    = (idx >> 11) & 15;
        int L    = idx >> 15;
        int g = lane >> 2, i = lane & 3;
        int n  = nf * 8 + g;
        int ks = (c & 7) * 32 + kg * 16;
        const float* W = (L == 0) ? (c < 8 ? Ws1 : Wn1) : (c < 8 ? Ws2 : Wn2);
        float w00 = W[n * 256 + ks + 2 * i];
        float w01 = W[n * 256 + ks + 2 * i + 1];
        float w10 = W[n * 256 + ks + 2 * i + 8];
        float w11 = W[n * 256 + ks + 2 * i + 9];
        uint32_t b0h, b0l, b1h, b1l;
        bfsplit2(w00, w01, b0h, b0l);
        bfsplit2(w10, w11, b1h, b1l);
        uint4 o; o.x = b0h; o.y = b1h; o.z = b0l; o.w = b1l;
        g_bf[idx] = o;
    } else {
        // ---- spatial binning: one block per batch ----
        int b = bx - 2304;
        cnt[tid] = 0;
        if (tid == 0) cnt[256] = 0;
        __syncthreads();
        int mycell[8]; float2 myc[8];
        #pragma unroll
        for (int t = 0; t < 8; ++t) {
            int j = t * 256 + tid;
            float cx = cent[((size_t)b * NN + j) * 2];
            float cy = cent[((size_t)b * NN + j) * 2 + 1];
            myc[t] = make_float2(cx, cy);
            int cell = -1;
            if (!pad[b * NN + j]) {
                int ix = min(15, max(0, (int)(cx * 16.f)));
                int iy = min(15, max(0, (int)(cy * 16.f)));
                cell = iy * 16 + ix;
            }
            mycell[t] = cell;
            if (cell >= 0) atomicAdd(&cnt[cell], 1);
        }
        __syncthreads();
        if (tid == 0) {
            int s = 0;
            for (int c2 = 0; c2 < 256; ++c2) { cbase[c2] = s; s += cnt[c2]; }
            cbase[256] = s;
        }
        __syncthreads();
        g_cstart[b * 257 + tid] = cbase[tid];
        if (tid == 0) g_cstart[b * 257 + 256] = cbase[256];
        cnt[tid] = cbase[tid];
        __syncthreads();
        #pragma unroll
        for (int t = 0; t < 8; ++t) {
            if (mycell[t] >= 0) {
                int pos = atomicAdd(&cnt[mycell[t]], 1);
                g_spts[b * NN + pos] = myc[t];
                g_sidx[b * NN + pos] = t * 256 + tid;
            }
        }
    }
}

// ---------------- grid-binned exact kNN: 4 threads/query, ring expansion ----------------
__global__ void __launch_bounds__(256) knn_search(const float* __restrict__ cent,
                                                  const unsigned char* __restrict__ pad) {
    __shared__ float2 spts[NN];
    __shared__ int    sidx[NN];
    __shared__ int    cst[257];
    const u64 MX = 0xFFFFFFFFFFFFFFFFull;

    int b  = blockIdx.x >> 5;
    int cb = blockIdx.x & 31;
    int tid = threadIdx.x;
    for (int j = tid; j < NN; j += 256) {
        spts[j] = g_spts[b * NN + j];
        sidx[j] = g_sidx[b * NN + j];
    }
    cst[tid] = g_cstart[b * 257 + tid];
    if (tid == 0) cst[256] = g_cstart[b * 257 + 256];
    __syncthreads();

    int q  = cb * 64 + (tid >> 2);
    int st = tid & 3;
    int row = b * NN + q;
    float qx = cent[(size_t)row * 2], qy = cent[(size_t)row * 2 + 1];
    bool pq = pad[row] != 0;

    u64 heap[8];
    #pragma unroll
    for (int t = 0; t < 8; ++t) heap[t] = MX;

    if (!pq) {
        int cx = min(15, max(0, (int)(qx * 16.f)));
        int cy = min(15, max(0, (int)(qy * 16.f)));
        const float ch = 1.0f / 16.0f;
        for (int r = 1; r <= 16; ++r) {
            #pragma unroll
            for (int t = 0; t < 8; ++t) heap[t] = MX;
            int xlo = max(0, cx - r), xhi = min(15, cx + r);
            int ylo = max(0, cy - r), yhi = min(15, cy + r);
            for (int yy = ylo; yy <= yhi; ++yy) {
                int s0 = cst[yy * 16 + xlo];
                int e0 = cst[yy * 16 + xhi + 1];
                for (int j = s0 + st; j < e0; j += 4) {
                    float2 c = spts[j];
                    float dx = __fadd_rn(qx, -c.x);
                    float dy = __fadd_rn(qy, -c.y);
                    float d2 = __fadd_rn(__fmul_rn(dx, dx), __fmul_rn(dy, dy));
                    u64 key = ((u64)__float_as_uint(d2) << 32) | (uint32_t)sidx[j];
                    if (key < heap[7]) {
                        heap[7] = key;
                        #pragma unroll
                        for (int t = 7; t > 0; --t)
                            if (heap[t] < heap[t - 1]) { u64 w = heap[t]; heap[t] = heap[t - 1]; heap[t - 1] = w; }
                    }
                }
            }
            // merge quad (butterfly over xor 1, 2); snapshot partner first
            #pragma unroll
            for (int o = 1; o <= 2; o <<= 1) {
                u64 tmp[8];
                #pragma unroll
                for (int t = 0; t < 8; ++t) tmp[t] = __shfl_xor_sync(0xffffffffu, heap[t], o);
                #pragma unroll
                for (int t = 0; t < 8; ++t) {
                    if (tmp[t] < heap[7]) {
                        heap[7] = tmp[t];
                        #pragma unroll
                        for (int u2 = 7; u2 > 0; --u2)
                            if (heap[u2] < heap[u2 - 1]) { u64 w = heap[u2]; heap[u2] = heap[u2 - 1]; heap[u2 - 1] = w; }
                    }
                }
            }
            // stopping: 8th-best exact d2 strictly inside guaranteed-scanned radius
            float gl = (cx - r > 0)  ? (qx - (float)(cx - r) * ch)     : 1e30f;
            float gr = (cx + r < 15) ? ((float)(cx + r + 1) * ch - qx) : 1e30f;
            float gd = (cy - r > 0)  ? (qy - (float)(cy - r) * ch)     : 1e30f;
            float gu = (cy + r < 15) ? ((float)(cy + r + 1) * ch - qy) : 1e30f;
            float gm = fminf(fminf(gl, gr), fminf(gd, gu)) * 0.999f;
            bool cover = (cx - r <= 0) && (cx + r >= 15) && (cy - r <= 0) && (cy + r >= 15);
            bool full = heap[7] != MX;
            float d8 = __uint_as_float((uint32_t)(heap[7] >> 32));
            if (cover || (full && d8 < gm * gm)) break;
        }
    }

    if (st == 0) {
        int ro = row * KNB;
        if (pq) {
            #pragma unroll
            for (int k = 0; k < KNB; ++k) { g_nbr[ro + k] = 0; g_dist[ro + k] = INFD; }
        } else {
            // re-key by (sqrt(d2), idx) and sort (matches reference top_k ordering)
            u64 sk[8];
            #pragma unroll
            for (int t = 0; t < 8; ++t) {
                uint32_t d2b = (uint32_t)(heap[t] >> 32);
                if (d2b == 0xFFFFFFFFu) sk[t] = MX;
                else {
                    float s = sqrtf(fmaxf(__uint_as_float(d2b), 0.f));
                    sk[t] = ((u64)__float_as_uint(s) << 32) | (uint32_t)heap[t];
                }
            }
            #pragma unroll
            for (int a = 1; a < 8; ++a) {
                u64 v = sk[a]; int p = a;
                while (p > 0 && sk[p - 1] > v) { sk[p] = sk[p - 1]; --p; }
                sk[p] = v;
            }
            int outk = 0; bool skipped = false;
            #pragma unroll
            for (int t = 0; t < 8; ++t) {
                if (outk >= KNB) break;
                if (sk[t] == MX) break;
                uint32_t idx = (uint32_t)sk[t];
                if (!skipped && (int)idx == q) { skipped = true; continue; }
                float dd = __uint_as_float((uint32_t)(sk[t] >> 32));
                g_nbr[ro + outk] = (int)idx;
                g_dist[ro + outk] = dd;
                ++outk;
            }
            for (; outk < KNB; ++outk) { g_nbr[ro + outk] = 0; g_dist[ro + outk] = INFD; }
        }
    }
}

// ---------------- edge weights + fused layer-1 aggregation (R9-proven) ----------------
__global__ void __launch_bounds__(256) weight_agg_kernel(const float* __restrict__ h,
                                                         const unsigned char* __restrict__ pad,
                                                         const int* __restrict__ tids) {
    int warp = threadIdx.x >> 5, lane = threadIdx.x & 31;
    int row = blockIdx.x * 8 + warp;
    int b = row / NN;

    const float4* hp = (const float4*)(h + (size_t)row * HH);
    float4 qa = hp[lane * 2], qb = hp[lane * 2 + 1];
    float nq = fmaxf(g_norm[row], 1e-12f);

    float invd[6], sim[6]; int nb[6]; bool val[6];
    float sum_inv = 0.f, sum_sim = 0.f;
    #pragma unroll
    for (int k = 0; k < KNB; k++) {
        int idx  = g_nbr[row * KNB + k];
        float dk = g_dist[row * KNB + k];
        int nrow = b * NN + idx;
        const float4* np = (const float4*)(h + (size_t)nrow * HH);
        float4 na = np[lane * 2], nb4 = np[lane * 2 + 1];
        float dot = qa.x*na.x + qa.y*na.y + qa.z*na.z + qa.w*na.w
                  + qb.x*nb4.x + qb.y*nb4.y + qb.z*nb4.z + qb.w*nb4.w;
        #pragma unroll
        for (int o = 16; o; o >>= 1) dot += __shfl_xor_sync(0xffffffffu, dot, o);
        float nn = fmaxf(g_norm[nrow], 1e-12f);
        bool v = dk < 5e8f;
        float s  = v ? fmaxf(dot / (nq * nn), 0.f) : 0.f;
        float id = v ? (1.f / fmaxf(dk, 1e-4f)) : 0.f;
        invd[k] = id; sim[k] = s; nb[k] = idx; val[k] = v;
        sum_inv += id; sum_sim += s;
    }

    bool pq = pad[row] != 0;
    int tq = tids[row];
    float rs = 1.f / fmaxf(sum_inv, 1e-8f);
    float rm = 1.f / fmaxf(sum_sim, 1e-8f);
    float w[6]; float tot = 0.f;
    #pragma unroll
    for (int k = 0; k < KNB; k++) {
        float wk = 0.6f * invd[k] * rs + 0.4f * sim[k] * rm;
        int tnb = tids[b * NN + nb[k]];
        if (val[k] && (tq != tnb)) wk *= 1.2f;
        w[k] = wk; tot += wk;
    }
    float rt = 1.f / fmaxf(tot, 1e-8f);
    float wf[6];
    #pragma unroll
    for (int k = 0; k < KNB; k++) wf[k] = pq ? 0.f : w[k] * rt;
    if (lane == 0) {
        #pragma unroll
        for (int k = 0; k < KNB; k++) g_w[row * KNB + k] = wf[k];
    }

    float4 A0 = make_float4(0.f, 0.f, 0.f, 0.f);
    float4 A1 = make_float4(0.f, 0.f, 0.f, 0.f);
    #pragma unroll
    for (int k = 0; k < KNB; k++) {
        const float4* np = (const float4*)(h + (size_t)(b * NN + nb[k]) * HH);
        float4 na = np[lane * 2], nb4 = np[lane * 2 + 1];
        float wk = wf[k];
        A0.x = fmaf(wk, na.x, A0.x);  A0.y = fmaf(wk, na.y, A0.y);
        A0.z = fmaf(wk, na.z, A0.z);  A0.w = fmaf(wk, na.w, A0.w);
        A1.x = fmaf(wk, nb4.x, A1.x); A1.y = fmaf(wk, nb4.y, A1.y);
        A1.z = fmaf(wk, nb4.z, A1.z); A1.w = fmaf(wk, nb4.w, A1.w);
    }
    float4* op = (float4*)(g_agg + (size_t)row * HH);
    op[lane * 2]     = A0;
    op[lane * 2 + 1] = A1;
}

// ---------------- layer-2 aggregation (R2-proven) ----------------
__global__ void __launch_bounds__(256) agg_kernel(const float* __restrict__ h) {
    int row = blockIdx.x;
    int b = row >> 11;
    __shared__ float sw[KNB];
    __shared__ int   si[KNB];
    int t = threadIdx.x;
    if (t < KNB) { sw[t] = g_w[row * KNB + t]; si[t] = g_nbr[row * KNB + t]; }
    __syncthreads();
    float a = 0.f;
    #pragma unroll
    for (int k = 0; k < KNB; k++)
        a = fmaf(sw[k], h[((size_t)(b * NN + si[k])) * HH + t], a);
    g_agg[(size_t)row * HH + t] = a;
}

// ---------------- fused bf16x3 mma GEMM + GELU + LN + residual (R9-proven) ----------------
__global__ void __launch_bounds__(256, 2) gemm_ln_mma(
    const float* __restrict__ hin, int L,
    const float* __restrict__ gv, const float* __restrict__ bv,
    const unsigned char* __restrict__ pad,
    float* __restrict__ hout, int zero_pad)
{
    extern __shared__ char sm[];
    float* red1  = (float*)(sm + OFF_R1);
    float* red2  = (float*)(sm + OFF_R2);
    float* sgam  = (float*)(sm + OFF_GAM);
    float* sbet  = (float*)(sm + OFF_BET);
    uint32_t sb  = smem_u32(sm);

    int tid = threadIdx.x;
    int m0 = blockIdx.x * 64;
    int wid = tid >> 5, lane = tid & 31;
    int mw = wid >> 2, nw = wid & 3;
    int g = lane >> 2, i = lane & 3;

    sgam[tid] = gv[tid];
    sbet[tid] = bv[tid];

    float acc[2][8][4];
    #pragma unroll
    for (int a = 0; a < 2; a++)
        #pragma unroll
        for (int b2 = 0; b2 < 8; b2++)
            #pragma unroll
            for (int c2 = 0; c2 < 4; c2++) acc[a][b2][c2] = 0.f;

    const uint4* gbfL = g_bf + (size_t)L * 16 * 2048;
    int ar = tid >> 2;
    int kq = (tid & 3) * 8;

    float4 pv0, pv1;
    {
        const float* src = hin + (size_t)(m0 + ar) * HH + kq;
        pv0 = *(const float4*)src;
        pv1 = *(const float4*)(src + 4);
        #pragma unroll
        for (int t = 0; t < 8; ++t) {
            int f = t * 256 + tid;
            cp16(sb + OFF_B0 + f * 16, gbfL + f);
        }
        asm volatile("cp.async.commit_group;" ::: "memory");
    }

    #pragma unroll 1
    for (int c = 0; c < 16; ++c) {
        int cur = c & 1;
        uint32_t aoff = cur ? OFF_A1 : OFF_A0;
        uint32_t boff = cur ? OFF_B1 : OFF_B0;

        {
            uint32_t h0, l0, h1, l1, h2, l2, h3, l3;
            bfsplit2(pv0.x, pv0.y, h0, l0);
            bfsplit2(pv0.z, pv0.w, h1, l1);
            bfsplit2(pv1.x, pv1.y, h2, l2);
            bfsplit2(pv1.z, pv1.w, h3, l3);
            uint4* dst = (uint4*)(sm + aoff + (ar * PADP + (tid & 3) * 4) * 8);
            uint4 u0; u0.x = h0; u0.y = l0; u0.z = h1; u0.w = l1;
            uint4 u1; u1.x = h2; u1.y = l2; u1.z = h3; u1.w = l3;
            dst[0] = u0;
            dst[1] = u1;
        }
        asm volatile("cp.async.wait_group 0;" ::: "memory");
        __syncthreads();

        if (c < 15) {
            int cn = c + 1;
            const uint4* gsrc = gbfL + (size_t)cn * 2048;
            uint32_t bno = (cn & 1) ? OFF_B1 : OFF_B0;
            #pragma unroll
            for (int t = 0; t < 8; ++t) {
                int f = t * 256 + tid;
                cp16(sb + bno + f * 16, gsrc + f);
            }
            asm volatile("cp.async.commit_group;" ::: "memory");
            const float* asrc = (cn < 8 ? hin : g_agg)
                              + (size_t)(m0 + ar) * HH + (cn & 7) * 32 + kq;
            pv0 = *(const float4*)asrc;
            pv1 = *(const float4*)(asrc + 4);
        }

        const uint2* Ab = (const uint2*)(sm + aoff);
        const uint4* Bb = (const uint4*)(sm + boff);
        #pragma unroll
        for (int kg = 0; kg < 2; ++kg) {
            uint32_t ah[2][4], al[2][4];
            #pragma unroll
            for (int fm = 0; fm < 2; ++fm) {
                int ro = (mw * 32 + fm * 16 + g) * PADP + kg * 8 + i;
                uint2 x0 = Ab[ro];
                uint2 x1 = Ab[ro + 8 * PADP];
                uint2 x2 = Ab[ro + 4];
                uint2 x3 = Ab[ro + 8 * PADP + 4];
                ah[fm][0] = x0.x; ah[fm][1] = x1.x; ah[fm][2] = x2.x; ah[fm][3] = x3.x;
                al[fm][0] = x0.y; al[fm][1] = x1.y; al[fm][2] = x2.y; al[fm][3] = x3.y;
            }
            #pragma unroll
            for (int fn = 0; fn < 8; ++fn) {
                uint4 B = Bb[(kg * 32 + nw * 8 + fn) * 32 + lane];
                #pragma unroll
                for (int fm = 0; fm < 2; ++fm)
                    mma16(acc[fm][fn], ah[fm][0], ah[fm][1], ah[fm][2], ah[fm][3], B.x, B.y);
                #pragma unroll
                for (int fm = 0; fm < 2; ++fm)
                    mma16(acc[fm][fn], ah[fm][0], ah[fm][1], ah[fm][2], ah[fm][3], B.z, B.w);
                #pragma unroll
                for (int fm = 0; fm < 2; ++fm)
                    mma16(acc[fm][fn], al[fm][0], al[fm][1], al[fm][2], al[fm][3], B.x, B.y);
            }
        }
    }
    __syncthreads();

    float s1[4] = {0.f, 0.f, 0.f, 0.f};
    float s2[4] = {0.f, 0.f, 0.f, 0.f};
    #pragma unroll
    for (int fm = 0; fm < 2; ++fm)
        #pragma unroll
        for (int fn = 0; fn < 8; ++fn)
            #pragma unroll
            for (int cc = 0; cc < 4; ++cc) {
                float x = acc[fm][fn][cc];
                float gl = 0.5f * x * (1.0f + erff(x * 0.70710678118654752f));
                acc[fm][fn][cc] = gl;
                int rs = fm * 2 + (cc >> 1);
                s1[rs] += gl;
                s2[rs] = fmaf(gl, gl, s2[rs]);
            }
    #pragma unroll
    for (int rs = 0; rs < 4; ++rs) {
        #pragma unroll
        for (int o = 1; o <= 2; o <<= 1) {
            s1[rs] += __shfl_xor_sync(0xffffffffu, s1[rs], o);
            s2[rs] += __shfl_xor_sync(0xffffffffu, s2[rs], o);
        }
    }
    if (i == 0) {
        #pragma unroll
        for (int rs = 0; rs < 4; ++rs) {
            int row_l = mw * 32 + (rs >> 1) * 16 + g + (rs & 1) * 8;
            red1[row_l * 4 + nw] = s1[rs];
            red2[row_l * 4 + nw] = s2[rs];
        }
    }
    __syncthreads();

    #pragma unroll
    for (int fm = 0; fm < 2; ++fm) {
        #pragma unroll
        for (int rh = 0; rh < 2; ++rh) {
            int row_l = mw * 32 + fm * 16 + g + rh * 8;
            int row_g = m0 + row_l;
            float st  = red1[row_l * 4 + 0] + red1[row_l * 4 + 1]
                      + red1[row_l * 4 + 2] + red1[row_l * 4 + 3];
            float st2 = red2[row_l * 4 + 0] + red2[row_l * 4 + 1]
                      + red2[row_l * 4 + 2] + red2[row_l * 4 + 3];
            float mu   = st * (1.f / HH);
            float var  = fmaf(-mu, mu, st2 * (1.f / HH));
            float rstd = rsqrtf(var + 1e-5f);
            bool pz = (zero_pad != 0) && (pad[row_g] != 0);
            #pragma unroll
            for (int fn = 0; fn < 8; ++fn) {
                int col = nw * 64 + fn * 8 + 2 * i;
                float v0 = acc[fm][fn][rh * 2 + 0];
                float v1 = acc[fm][fn][rh * 2 + 1];
                float2 res = *(const float2*)(hin + (size_t)row_g * HH + col);
                float2 o;
                o.x = pz ? 0.f : res.x + (v0 - mu) * rstd * sgam[col]     + sbet[col];
                o.y = pz ? 0.f : res.y + (v1 - mu) * rstd * sgam[col + 1] + sbet[col + 1];
                *(float2*)(hout + (size_t)row_g * HH + col) = o;
            }
        }
    }
}

// ---------------- launcher ----------------
extern "C" void kernel_launch(void* const* d_in, const int* in_sizes, int n_in,
                              void* d_out, int out_size) {
    const float*         h0   = (const float*)d_in[0];
    const unsigned char* pad  = (const unsigned char*)d_in[1];
    const float*         cent = (const float*)d_in[2];
    const int*           tids = (const int*)d_in[3];
    const float* Ws1 = (const float*)d_in[4];
    const float* Wn1 = (const float*)d_in[5];
    const float* g1  = (const float*)d_in[6];
    const float* b1  = (const float*)d_in[7];
    const float* Ws2 = (const float*)d_in[8];
    const float* Wn2 = (const float*)d_in[9];
    const float* g2  = (const float*)d_in[10];
    const float* b2  = (const float*)d_in[11];
    float* out = (float*)d_out;

    float* h1;
    cudaGetSymbolAddress((void**)&h1, g_h1);

    cudaFuncSetAttribute(gemm_ln_mma, cudaFuncAttributeMaxDynamicSharedMemorySize, SMEM_TOTAL);

    combo_kernel     <<<2312, 256>>>(h0, Ws1, Wn1, Ws2, Wn2, cent, pad);  // 0
    knn_search       <<<256, 256>>>(cent, pad);                            // 1
    weight_agg_kernel<<<MM / 8, 256>>>(h0, pad, tids);                     // 2
    gemm_ln_mma<<<MM / 64, 256, SMEM_TOTAL>>>(h0, 0, g1, b1, pad, h1, 0);  // 3
    agg_kernel       <<<MM, 256>>>(h1);                                    // 4
    gemm_ln_mma<<<MM / 64, 256, SMEM_TOTAL>>>(h1, 1, g2, b2, pad, out, 1); // 5 (profiled)
}